// round 6
// baseline (speedup 1.0000x reference)
#include <cuda_runtime.h>
#include <cuda_fp16.h>

#define RES 512
#define RANK 32
#define CELLS (RES * RES)
#define N_POINTS (8192 * 128)

// Duplicated-pair fp16 layout: per plane, per cell (y,x): 128 bytes =
// for r in 0..31: half2{ v(y,x,r), v(y,min(x+1,RES-1),r) } at half-index 2r.
__device__ __half g_tp[3][(size_t)CELLS * 2 * RANK];

// Encoded per-dim bbox of raw pts: [min_x,min_y,min_z, max_x,max_y,max_z]
__device__ unsigned int g_bbox[6];

__device__ __forceinline__ unsigned int encodeF(float f) {
    unsigned int b = __float_as_uint(f);
    return (b & 0x80000000u) ? ~b : (b | 0x80000000u);
}
__device__ __forceinline__ float decodeF(unsigned int u) {
    return (u & 0x80000000u) ? __uint_as_float(u ^ 0x80000000u)
                             : __uint_as_float(~u);
}

// ---------------------------------------------------------------------------
// Kernel 0: reset bbox accumulators
// ---------------------------------------------------------------------------
__global__ void init_kernel() {
    int t = threadIdx.x;
    if (t < 3) g_bbox[t] = 0xFFFFFFFFu;
    else if (t < 6) g_bbox[t] = 0u;
}

// ---------------------------------------------------------------------------
// Kernel 1: per-dimension min/max of raw pts (stride divisible by 3).
// ---------------------------------------------------------------------------
__global__ void __launch_bounds__(256) bbox_kernel(const float* __restrict__ pts) {
    const int t = blockIdx.x * 256 + threadIdx.x;
    const int stride = 384 * 256;
    const int dim = t % 3;
    float mn = 3.0e38f, mx = -3.0e38f;
    for (int i = t; i < N_POINTS * 3; i += stride) {
        const float v = __ldg(&pts[i]);
        mn = fminf(mn, v);
        mx = fmaxf(mx, v);
    }
    __shared__ unsigned int smn[3], smx[3];
    if (threadIdx.x < 3) { smn[threadIdx.x] = 0xFFFFFFFFu; smx[threadIdx.x] = 0u; }
    __syncthreads();
    atomicMin(&smn[dim], encodeF(mn));
    atomicMax(&smx[dim], encodeF(mx));
    __syncthreads();
    if (threadIdx.x < 3) {
        atomicMin(&g_bbox[threadIdx.x], smn[threadIdx.x]);
        atomicMax(&g_bbox[3 + threadIdx.x], smx[threadIdx.x]);
    }
}

// ---------------------------------------------------------------------------
// Kernel 2: [RANK,H,W] f32 -> dup-pair fp16 layout, bbox-gated.
// Block = 32 consecutive cells of one row x all ranks; loads 33 columns.
// ---------------------------------------------------------------------------
__global__ void __launch_bounds__(256) transpose_kernel(const float* __restrict__ gxy,
                                                        const float* __restrict__ gxz,
                                                        const float* __restrict__ gyz,
                                                        const float* __restrict__ aabb) {
    const int plane = blockIdx.y;
    const int c0 = blockIdx.x * 32;
    const int row = c0 >> 9;
    const int col0 = c0 & (RES - 1);

    const int cdim = (plane == 2) ? 1 : 0;
    const int rdim = (plane == 0) ? 1 : 2;

    {
        const float a0c = aabb[cdim], sc = (float)(RES - 1) / (aabb[3 + cdim] - aabb[cdim]);
        const float a0r = aabb[rdim], sr = (float)(RES - 1) / (aabb[3 + rdim] - aabb[rdim]);
        const float gminc = (decodeF(g_bbox[cdim]) - a0c) * sc;
        const float gmaxc = (decodeF(g_bbox[3 + cdim]) - a0c) * sc;
        const float gminr = (decodeF(g_bbox[rdim]) - a0r) * sr;
        const float gmaxr = (decodeF(g_bbox[3 + rdim]) - a0r) * sr;
        const int cmin = min(max(__float2int_rd(gminc), 0), RES - 1);
        const int cmax = min(min(max(__float2int_rd(gmaxc), 0), RES - 1) + 1, RES - 1);
        const int rmin = min(max(__float2int_rd(gminr), 0), RES - 1);
        const int rmax = min(min(max(__float2int_rd(gmaxr), 0), RES - 1) + 1, RES - 1);
        if (row < rmin || row > rmax || col0 > cmax || col0 + 31 < cmin) return;
    }

    __shared__ float tile[RANK][34];
    const float* __restrict__ src = (plane == 0) ? gxy : (plane == 1) ? gxz : gyz;

    const int t = threadIdx.x;
    const int w = t >> 5;
    const int l = t & 31;

#pragma unroll
    for (int i = 0; i < 4; i++) {
        const int r = w + i * 8;
        tile[r][l] = src[(size_t)r * CELLS + c0 + l];
    }
    // 33rd column (x+1 of last cell), clamped at row edge
    if (t < RANK) {
        const int srccol = (col0 + 32 <= RES - 1) ? (c0 + 32) : (c0 + 31);
        tile[t][32] = src[(size_t)t * CELLS + srccol];
    }
    __syncthreads();

    __half* __restrict__ dst = g_tp[plane];
#pragma unroll
    for (int k = 0; k < 2; k++) {
        const int item = t + k * 256;
        const int cell = item >> 4;          // local cell 0..31
        const int rp = (item & 15) * 2;      // rank pair rp, rp+1
        const int xg = col0 + cell;
        const int nb = (xg < RES - 1) ? cell + 1 : cell;  // x+1 clamp
        const __half2 v0 = __floats2half2_rn(tile[rp][cell], tile[rp][nb]);
        const __half2 v1 = __floats2half2_rn(tile[rp + 1][cell], tile[rp + 1][nb]);
        // entry for cell: 64 halves; rank r half2 at half-index 2r
        __half2* outp = reinterpret_cast<__half2*>(dst + (size_t)(c0 + cell) * 64 + rp * 2);
        outp[0] = v0;
        outp[1] = v1;
    }
}

// ---------------------------------------------------------------------------
// Kernel 3: triplane sample. 8 lanes/point; lane j = ranks 4j..4j+3.
// Per plane: 2 loads (rows y0,y1), each one aligned 128B line (1 wavefront).
// ---------------------------------------------------------------------------
struct Corners {
    unsigned int o0, o1;   // byte offsets of (y0,x0) and (y1,x0) entries
    float wx, wy;
};

__device__ __forceinline__ Corners make_corners(float cx, float cy) {
    const float gx = ((cx + 1.0f) * 0.5f) * (float)(RES - 1);
    const float gy = ((cy + 1.0f) * 0.5f) * (float)(RES - 1);
    Corners c;
    c.wx = gx - floorf(gx);
    c.wy = gy - floorf(gy);
    const int x0 = min(max(__float2int_rd(gx), 0), RES - 1);
    const int y0 = min(max(__float2int_rd(gy), 0), RES - 1);
    const int dy = (min(y0 + 1, RES - 1) - y0) << 16;  // row stride = 512*128B
    c.o0 = (unsigned int)(((y0 << 9) + x0) << 7);
    c.o1 = c.o0 + dy;
    return c;
}

// Per-lane: E/F = 4 half2 (x0,x1) pairs for ranks 4j..4j+3, rows y0/y1.
// Returns s2[r] = (s,s) duplicated bilinear sample per rank.
__device__ __forceinline__ void bilin_pair(const uint4& E, const uint4& F,
                                           __half2 a2, __half2 b2, __half2 s2[4]) {
    const __half2* e = reinterpret_cast<const __half2*>(&E);
    const __half2* f = reinterpret_cast<const __half2*>(&F);
#pragma unroll
    for (int r = 0; r < 4; r++) {
        __half2 acc = __hmul2(e[r], a2);
        acc = __hfma2(f[r], b2, acc);
        s2[r] = __hadd2(acc, __lowhigh2highlow(acc));  // horizontal: (s,s)
    }
}

__global__ void __launch_bounds__(256) sample_kernel(const float* __restrict__ pts,
                                                     const float* __restrict__ aabb,
                                                     float* __restrict__ out) {
    const int tid = blockIdx.x * blockDim.x + threadIdx.x;
    const int j = tid & 7;             // rank quad 0..7 (4 ranks each)
    const int point = tid >> 3;        // 8 lanes per point

    const float px = __ldg(&pts[point * 3 + 0]);
    const float py = __ldg(&pts[point * 3 + 1]);
    const float pz = __ldg(&pts[point * 3 + 2]);

    const float a0x = __ldg(&aabb[0]), a0y = __ldg(&aabb[1]), a0z = __ldg(&aabb[2]);
    const float a1x = __ldg(&aabb[3]), a1y = __ldg(&aabb[4]), a1z = __ldg(&aabb[5]);

    const float nx = (px - a0x) * (2.0f / (a1x - a0x)) - 1.0f;
    const float ny = (py - a0y) * (2.0f / (a1y - a0y)) - 1.0f;
    const float nz = (pz - a0z) * (2.0f / (a1z - a0z)) - 1.0f;

    const Corners cxy = make_corners(nx, ny);
    const Corners cxz = make_corners(nx, nz);
    const Corners cyz = make_corners(ny, nz);

    const char* __restrict__ P0 = reinterpret_cast<const char*>(g_tp[0]);
    const char* __restrict__ P1 = reinterpret_cast<const char*>(g_tp[1]);
    const char* __restrict__ P2 = reinterpret_cast<const char*>(g_tp[2]);
    const unsigned int lo = (unsigned int)j << 4;

    // 6 loads, each a full aligned 128B line per 8-lane group
    const uint4 E0 = *reinterpret_cast<const uint4*>(P0 + cxy.o0 + lo);
    const uint4 F0 = *reinterpret_cast<const uint4*>(P0 + cxy.o1 + lo);
    const uint4 E1 = *reinterpret_cast<const uint4*>(P1 + cxz.o0 + lo);
    const uint4 F1 = *reinterpret_cast<const uint4*>(P1 + cxz.o1 + lo);
    const uint4 E2 = *reinterpret_cast<const uint4*>(P2 + cyz.o0 + lo);
    const uint4 F2 = *reinterpret_cast<const uint4*>(P2 + cyz.o1 + lo);

    // Weights: a2 = ((1-wx)(1-wy), wx(1-wy)) applies to row y0 pair (x0,x1);
    //          b2 = ((1-wx)wy,     wx*wy)    applies to row y1 pair.
    const __half2 a2_0 = __floats2half2_rn((1.0f - cxy.wx) * (1.0f - cxy.wy), cxy.wx * (1.0f - cxy.wy));
    const __half2 b2_0 = __floats2half2_rn((1.0f - cxy.wx) * cxy.wy, cxy.wx * cxy.wy);
    const __half2 a2_1 = __floats2half2_rn((1.0f - cxz.wx) * (1.0f - cxz.wy), cxz.wx * (1.0f - cxz.wy));
    const __half2 b2_1 = __floats2half2_rn((1.0f - cxz.wx) * cxz.wy, cxz.wx * cxz.wy);
    const __half2 a2_2 = __floats2half2_rn((1.0f - cyz.wx) * (1.0f - cyz.wy), cyz.wx * (1.0f - cyz.wy));
    const __half2 b2_2 = __floats2half2_rn((1.0f - cyz.wx) * cyz.wy, cyz.wx * cyz.wy);

    __half2 sxy[4], sxz[4], syz[4];
    bilin_pair(E0, F0, a2_0, b2_0, sxy);
    bilin_pair(E1, F1, a2_1, b2_1, sxz);
    bilin_pair(E2, F2, a2_2, b2_2, syz);

    // Triple product + accumulate (values duplicated in both halves)
    __half2 acc = __hmul2(__hmul2(sxy[0], sxz[0]), syz[0]);
#pragma unroll
    for (int r = 1; r < 4; r++) {
        acc = __hfma2(__hmul2(sxy[r], sxz[r]), syz[r], acc);
    }
    float sum = __low2float(acc);

    // Reduce across the 8-lane group
    sum += __shfl_xor_sync(0xffffffffu, sum, 1);
    sum += __shfl_xor_sync(0xffffffffu, sum, 2);
    sum += __shfl_xor_sync(0xffffffffu, sum, 4);

    if (j == 0) {
        out[point] = expf(sum * (1.0f / (float)RANK));
    }
}

extern "C" void kernel_launch(void* const* d_in, const int* in_sizes, int n_in,
                              void* d_out, int out_size) {
    const float* pts  = (const float*)d_in[0];
    const float* gxy  = (const float*)d_in[1];
    const float* gxz  = (const float*)d_in[2];
    const float* gyz  = (const float*)d_in[3];
    const float* aabb = (const float*)d_in[4];
    float* out = (float*)d_out;

    init_kernel<<<1, 32>>>();
    bbox_kernel<<<384, 256>>>(pts);
    transpose_kernel<<<dim3(CELLS / 32, 3), 256>>>(gxy, gxz, gyz, aabb);

    // 8 lanes/point -> 32 points per 256-thread block
    sample_kernel<<<N_POINTS / 32, 256>>>(pts, aabb, out);
}

// round 7
// speedup vs baseline: 1.3894x; 1.3894x over previous
#include <cuda_runtime.h>
#include <cuda_fp16.h>

#define RES 512
#define RANK 32
#define CELLS (RES * RES)
#define N_POINTS (8192 * 128)

// e5m2 dup-pair layout: per plane, per cell (y,x): 64 bytes.
// Byte 2r   = e5m2( v(y, x,   r) )
// Byte 2r+1 = e5m2( v(y, x+1, r) )   (x+1 clamped at row edge)
// e5m2 byte b decodes EXACTLY to the fp16 with bits (b << 8).
__device__ unsigned char g_tp[3][(size_t)CELLS * 2 * RANK];

// Encoded per-dim bbox of raw pts: [min_x,min_y,min_z, max_x,max_y,max_z]
__device__ unsigned int g_bbox[6];

__device__ __forceinline__ unsigned int encodeF(float f) {
    unsigned int b = __float_as_uint(f);
    return (b & 0x80000000u) ? ~b : (b | 0x80000000u);
}
__device__ __forceinline__ float decodeF(unsigned int u) {
    return (u & 0x80000000u) ? __uint_as_float(u ^ 0x80000000u)
                             : __uint_as_float(~u);
}

// f32 -> e5m2 byte, round-to-nearest via fp16 + mantissa-rounding add.
__device__ __forceinline__ unsigned int enc_e5m2(float v) {
    const unsigned int u = (unsigned int)__half_as_ushort(__float2half_rn(v));
    return ((u + 0x80u) >> 8) & 0xFFu;
}

// ---------------------------------------------------------------------------
// Kernel 0: reset bbox accumulators
// ---------------------------------------------------------------------------
__global__ void init_kernel() {
    int t = threadIdx.x;
    if (t < 3) g_bbox[t] = 0xFFFFFFFFu;
    else if (t < 6) g_bbox[t] = 0u;
}

// ---------------------------------------------------------------------------
// Kernel 1: per-dimension min/max of raw pts (stride divisible by 3).
// ---------------------------------------------------------------------------
__global__ void __launch_bounds__(256) bbox_kernel(const float* __restrict__ pts) {
    const int t = blockIdx.x * 256 + threadIdx.x;
    const int stride = 384 * 256;
    const int dim = t % 3;
    float mn = 3.0e38f, mx = -3.0e38f;
    for (int i = t; i < N_POINTS * 3; i += stride) {
        const float v = __ldg(&pts[i]);
        mn = fminf(mn, v);
        mx = fmaxf(mx, v);
    }
    __shared__ unsigned int smn[3], smx[3];
    if (threadIdx.x < 3) { smn[threadIdx.x] = 0xFFFFFFFFu; smx[threadIdx.x] = 0u; }
    __syncthreads();
    atomicMin(&smn[dim], encodeF(mn));
    atomicMax(&smx[dim], encodeF(mx));
    __syncthreads();
    if (threadIdx.x < 3) {
        atomicMin(&g_bbox[threadIdx.x], smn[threadIdx.x]);
        atomicMax(&g_bbox[3 + threadIdx.x], smx[threadIdx.x]);
    }
}

// ---------------------------------------------------------------------------
// Kernel 2: [RANK,H,W] f32 -> e5m2 dup-pair layout, bbox-gated.
// Block = 64 consecutive cells of one row x all 32 ranks (tiles never cross rows).
// ---------------------------------------------------------------------------
__global__ void __launch_bounds__(256) transpose_kernel(const float* __restrict__ gxy,
                                                        const float* __restrict__ gxz,
                                                        const float* __restrict__ gyz,
                                                        const float* __restrict__ aabb) {
    const int plane = blockIdx.y;
    const int c0 = blockIdx.x * 64;
    const int row = c0 >> 9;
    const int col0 = c0 & (RES - 1);

    const int cdim = (plane == 2) ? 1 : 0;
    const int rdim = (plane == 0) ? 1 : 2;

    {   // bbox gate
        const float a0c = aabb[cdim], sc = (float)(RES - 1) / (aabb[3 + cdim] - aabb[cdim]);
        const float a0r = aabb[rdim], sr = (float)(RES - 1) / (aabb[3 + rdim] - aabb[rdim]);
        const float gminc = (decodeF(g_bbox[cdim]) - a0c) * sc;
        const float gmaxc = (decodeF(g_bbox[3 + cdim]) - a0c) * sc;
        const float gminr = (decodeF(g_bbox[rdim]) - a0r) * sr;
        const float gmaxr = (decodeF(g_bbox[3 + rdim]) - a0r) * sr;
        const int cmin = min(max(__float2int_rd(gminc), 0), RES - 1);
        const int cmax = min(min(max(__float2int_rd(gmaxc), 0), RES - 1) + 1, RES - 1);
        const int rmin = min(max(__float2int_rd(gminr), 0), RES - 1);
        const int rmax = min(min(max(__float2int_rd(gmaxr), 0), RES - 1) + 1, RES - 1);
        if (row < rmin || row > rmax || col0 > cmax || col0 + 63 < cmin) return;
    }

    __shared__ float tile[RANK][67];  // cols 0..64 used; 67 avoids bank conflicts
    const float* __restrict__ src = (plane == 0) ? gxy : (plane == 1) ? gxz : gyz;

    const int t = threadIdx.x;

    // Load 32 ranks x 64 cols, coalesced
#pragma unroll
    for (int i = 0; i < 8; i++) {
        const int idx = t + i * 256;
        const int r = idx >> 6;
        const int c = idx & 63;
        tile[r][c] = src[(size_t)r * CELLS + c0 + c];
    }
    // 65th column (x+1 of last cell), clamped at row edge
    if (t < RANK) {
        const int srccol = (col0 + 64 <= RES - 1) ? (c0 + 64) : (c0 + 63);
        tile[t][64] = src[(size_t)t * CELLS + srccol];
    }
    __syncthreads();

    // Write: thread t -> cell (t>>2), quad j = t&3 covers ranks 8j..8j+7 (16 B)
    {
        const int cell = t >> 2;
        const int j = t & 3;
        const int xg = col0 + cell;
        const int nb = (xg < RES - 1) ? cell + 1 : cell;  // x+1 clamp
        uint4 w;
        unsigned int* wp = &w.x;
#pragma unroll
        for (int k = 0; k < 4; k++) {
            const int r0 = 8 * j + 2 * k;
            const unsigned int b0 = enc_e5m2(tile[r0][cell]);
            const unsigned int b1 = enc_e5m2(tile[r0][nb]);
            const unsigned int b2 = enc_e5m2(tile[r0 + 1][cell]);
            const unsigned int b3 = enc_e5m2(tile[r0 + 1][nb]);
            wp[k] = b0 | (b1 << 8) | (b2 << 16) | (b3 << 24);
        }
        *reinterpret_cast<uint4*>(&g_tp[plane][((size_t)(c0 + cell) << 6) + (j << 4)]) = w;
    }
}

// ---------------------------------------------------------------------------
// Kernel 3: triplane sample. 4 lanes/point (8 points/warp); lane j = ranks 8j..8j+7.
// Cell entry = 64 B e5m2 -> one load per plane-row covers the full entry:
// 6 loads, 6 L1 line-touches per point. Decode = 1 PRMT per rank-row (exact).
// ---------------------------------------------------------------------------
struct Corners {
    unsigned int o0, o1;   // byte offsets of (y0,x0) and (y1,x0) entries
    float wx, wy;
};

__device__ __forceinline__ Corners make_corners(float cx, float cy) {
    const float gx = ((cx + 1.0f) * 0.5f) * (float)(RES - 1);
    const float gy = ((cy + 1.0f) * 0.5f) * (float)(RES - 1);
    Corners c;
    c.wx = gx - floorf(gx);
    c.wy = gy - floorf(gy);
    const int x0 = min(max(__float2int_rd(gx), 0), RES - 1);
    const int y0 = min(max(__float2int_rd(gy), 0), RES - 1);
    const int dy = (min(y0 + 1, RES - 1) - y0) << 15;  // row stride = 512*64 B
    c.o0 = (unsigned int)(((y0 << 9) + x0) << 6);
    c.o1 = c.o0 + dy;
    return c;
}

// Per-plane: E (row y0), F (row y1): 4 u32 words, each = 2 ranks of (x0,x1) e5m2.
// pair[r] = a2*(x0,x1)@y0 + b2*(x0,x1)@y1  (8 half2 pairs, one per rank)
__device__ __forceinline__ void plane_pairs(const uint4& E, const uint4& F,
                                            __half2 a2, __half2 b2, __half2 pair[8]) {
    const unsigned int* e = &E.x;
    const unsigned int* f = &F.x;
#pragma unroll
    for (int k = 0; k < 4; k++) {
        // even rank of word k
        __half2 p0 = __halves2half2(__ushort_as_half(0), __ushort_as_half(0));
        unsigned int u0 = __byte_perm(e[k], 0, 0x1404);
        unsigned int u1 = __byte_perm(f[k], 0, 0x1404);
        __half2 h0 = *reinterpret_cast<__half2*>(&u0);
        __half2 h1 = *reinterpret_cast<__half2*>(&u1);
        pair[2 * k] = __hfma2(h1, b2, __hmul2(h0, a2));
        // odd rank of word k
        unsigned int v0 = __byte_perm(e[k], 0, 0x3424);
        unsigned int v1 = __byte_perm(f[k], 0, 0x3424);
        __half2 g0 = *reinterpret_cast<__half2*>(&v0);
        __half2 g1 = *reinterpret_cast<__half2*>(&v1);
        pair[2 * k + 1] = __hfma2(g1, b2, __hmul2(g0, a2));
        (void)p0;
    }
}

__global__ void __launch_bounds__(256) sample_kernel(const float* __restrict__ pts,
                                                     const float* __restrict__ aabb,
                                                     float* __restrict__ out) {
    const int tid = blockIdx.x * blockDim.x + threadIdx.x;
    const int j = tid & 3;             // rank octet 0..3 (8 ranks each)
    const int point = tid >> 2;        // 4 lanes per point

    const float px = __ldg(&pts[point * 3 + 0]);
    const float py = __ldg(&pts[point * 3 + 1]);
    const float pz = __ldg(&pts[point * 3 + 2]);

    const float a0x = __ldg(&aabb[0]), a0y = __ldg(&aabb[1]), a0z = __ldg(&aabb[2]);
    const float a1x = __ldg(&aabb[3]), a1y = __ldg(&aabb[4]), a1z = __ldg(&aabb[5]);

    const float nx = (px - a0x) * (2.0f / (a1x - a0x)) - 1.0f;
    const float ny = (py - a0y) * (2.0f / (a1y - a0y)) - 1.0f;
    const float nz = (pz - a0z) * (2.0f / (a1z - a0z)) - 1.0f;

    const Corners cxy = make_corners(nx, ny);
    const Corners cxz = make_corners(nx, nz);
    const Corners cyz = make_corners(ny, nz);

    const char* __restrict__ P0 = reinterpret_cast<const char*>(g_tp[0]);
    const char* __restrict__ P1 = reinterpret_cast<const char*>(g_tp[1]);
    const char* __restrict__ P2 = reinterpret_cast<const char*>(g_tp[2]);
    const unsigned int lo = (unsigned int)j << 4;

    // 6 loads; each covers a full 64 B cell entry across the 4-lane group
    const uint4 E0 = *reinterpret_cast<const uint4*>(P0 + cxy.o0 + lo);
    const uint4 F0 = *reinterpret_cast<const uint4*>(P0 + cxy.o1 + lo);
    const uint4 E1 = *reinterpret_cast<const uint4*>(P1 + cxz.o0 + lo);
    const uint4 F1 = *reinterpret_cast<const uint4*>(P1 + cxz.o1 + lo);
    const uint4 E2 = *reinterpret_cast<const uint4*>(P2 + cyz.o0 + lo);
    const uint4 F2 = *reinterpret_cast<const uint4*>(P2 + cyz.o1 + lo);

    // Weights: a2 = ((1-wx)(1-wy), wx(1-wy)) on row y0; b2 = ((1-wx)wy, wx*wy) on y1.
    const __half2 a2_0 = __floats2half2_rn((1.0f - cxy.wx) * (1.0f - cxy.wy), cxy.wx * (1.0f - cxy.wy));
    const __half2 b2_0 = __floats2half2_rn((1.0f - cxy.wx) * cxy.wy, cxy.wx * cxy.wy);
    const __half2 a2_1 = __floats2half2_rn((1.0f - cxz.wx) * (1.0f - cxz.wy), cxz.wx * (1.0f - cxz.wy));
    const __half2 b2_1 = __floats2half2_rn((1.0f - cxz.wx) * cxz.wy, cxz.wx * cxz.wy);
    const __half2 a2_2 = __floats2half2_rn((1.0f - cyz.wx) * (1.0f - cyz.wy), cyz.wx * (1.0f - cyz.wy));
    const __half2 b2_2 = __floats2half2_rn((1.0f - cyz.wx) * cyz.wy, cyz.wx * cyz.wy);

    __half2 pA[8], pB[8], pC[8];
    plane_pairs(E0, F0, a2_0, b2_0, pA);
    plane_pairs(E1, F1, a2_1, b2_1, pB);
    plane_pairs(E2, F2, a2_2, b2_2, pC);

    // Plane A keeps its (x0,x1) pair; B and C are horizontalized to (s,s).
    // acc accumulates (A0*sB*sC, A1*sB*sC); final low+high gives (A0+A1)*sB*sC.
    __half2 acc = __floats2half2_rn(0.0f, 0.0f);
#pragma unroll
    for (int r = 0; r < 8; r++) {
        const __half2 sB = __hadd2(pB[r], __lowhigh2highlow(pB[r]));
        const __half2 sC = __hadd2(pC[r], __lowhigh2highlow(pC[r]));
        acc = __hfma2(__hmul2(pA[r], sB), sC, acc);
    }
    float sum = __low2float(acc) + __high2float(acc);

    // Reduce across the 4-lane group
    sum += __shfl_xor_sync(0xffffffffu, sum, 1, 4);
    sum += __shfl_xor_sync(0xffffffffu, sum, 2, 4);

    if (j == 0) {
        out[point] = expf(sum * (1.0f / (float)RANK));
    }
}

extern "C" void kernel_launch(void* const* d_in, const int* in_sizes, int n_in,
                              void* d_out, int out_size) {
    const float* pts  = (const float*)d_in[0];
    const float* gxy  = (const float*)d_in[1];
    const float* gxz  = (const float*)d_in[2];
    const float* gyz  = (const float*)d_in[3];
    const float* aabb = (const float*)d_in[4];
    float* out = (float*)d_out;

    init_kernel<<<1, 32>>>();
    bbox_kernel<<<384, 256>>>(pts);
    transpose_kernel<<<dim3(CELLS / 64, 3), 256>>>(gxy, gxz, gyz, aabb);

    // 4 lanes/point -> 64 points per 256-thread block
    sample_kernel<<<N_POINTS / 64, 256>>>(pts, aabb, out);
}

// round 8
// speedup vs baseline: 1.4917x; 1.0736x over previous
#include <cuda_runtime.h>
#include <cuda_fp16.h>

#define RES 512
#define RANK 32
#define CELLS (RES * RES)
#define N_POINTS (8192 * 128)

// e5m2 dup-pair layout: per plane, per cell (y,x): 64 bytes.
// Word k of 16B group j holds bytes [r@x0, r@x1, r+1@x0, r+1@x1], r = 8j+2k.
// e5m2 byte b decodes EXACTLY to the fp16 with bits (b << 8).
__device__ unsigned char g_tp[3][(size_t)CELLS * 2 * RANK];

// Encoded per-dim bbox of raw pts: [min_x,min_y,min_z, max_x,max_y,max_z]
__device__ unsigned int g_bbox[6];

__device__ __forceinline__ unsigned int encodeF(float f) {
    unsigned int b = __float_as_uint(f);
    return (b & 0x80000000u) ? ~b : (b | 0x80000000u);
}
__device__ __forceinline__ float decodeF(unsigned int u) {
    return (u & 0x80000000u) ? __uint_as_float(u ^ 0x80000000u)
                             : __uint_as_float(~u);
}

// f32 -> e5m2 byte, round-to-nearest via fp16 + mantissa-rounding add.
__device__ __forceinline__ unsigned int enc_e5m2(float v) {
    const unsigned int u = (unsigned int)__half_as_ushort(__float2half_rn(v));
    return ((u + 0x80u) >> 8) & 0xFFu;
}

// ---------------------------------------------------------------------------
// Kernel 0: reset bbox accumulators
// ---------------------------------------------------------------------------
__global__ void init_kernel() {
    int t = threadIdx.x;
    if (t < 3) g_bbox[t] = 0xFFFFFFFFu;
    else if (t < 6) g_bbox[t] = 0u;
}

// ---------------------------------------------------------------------------
// Kernel 1: per-dimension min/max of raw pts (stride divisible by 3).
// ---------------------------------------------------------------------------
__global__ void __launch_bounds__(256) bbox_kernel(const float* __restrict__ pts) {
    const int t = blockIdx.x * 256 + threadIdx.x;
    const int stride = 384 * 256;
    const int dim = t % 3;
    float mn = 3.0e38f, mx = -3.0e38f;
    for (int i = t; i < N_POINTS * 3; i += stride) {
        const float v = __ldg(&pts[i]);
        mn = fminf(mn, v);
        mx = fmaxf(mx, v);
    }
    __shared__ unsigned int smn[3], smx[3];
    if (threadIdx.x < 3) { smn[threadIdx.x] = 0xFFFFFFFFu; smx[threadIdx.x] = 0u; }
    __syncthreads();
    atomicMin(&smn[dim], encodeF(mn));
    atomicMax(&smx[dim], encodeF(mx));
    __syncthreads();
    if (threadIdx.x < 3) {
        atomicMin(&g_bbox[threadIdx.x], smn[threadIdx.x]);
        atomicMax(&g_bbox[3 + threadIdx.x], smx[threadIdx.x]);
    }
}

// ---------------------------------------------------------------------------
// Kernel 2: [RANK,H,W] f32 -> e5m2 dup-pair layout, bbox-gated.
// Block = 64 consecutive cells of one row x all 32 ranks (tiles never cross rows).
// ---------------------------------------------------------------------------
__global__ void __launch_bounds__(256) transpose_kernel(const float* __restrict__ gxy,
                                                        const float* __restrict__ gxz,
                                                        const float* __restrict__ gyz,
                                                        const float* __restrict__ aabb) {
    const int plane = blockIdx.y;
    const int c0 = blockIdx.x * 64;
    const int row = c0 >> 9;
    const int col0 = c0 & (RES - 1);

    const int cdim = (plane == 2) ? 1 : 0;
    const int rdim = (plane == 0) ? 1 : 2;

    {   // bbox gate
        const float a0c = aabb[cdim], sc = (float)(RES - 1) / (aabb[3 + cdim] - aabb[cdim]);
        const float a0r = aabb[rdim], sr = (float)(RES - 1) / (aabb[3 + rdim] - aabb[rdim]);
        const float gminc = (decodeF(g_bbox[cdim]) - a0c) * sc;
        const float gmaxc = (decodeF(g_bbox[3 + cdim]) - a0c) * sc;
        const float gminr = (decodeF(g_bbox[rdim]) - a0r) * sr;
        const float gmaxr = (decodeF(g_bbox[3 + rdim]) - a0r) * sr;
        const int cmin = min(max(__float2int_rd(gminc), 0), RES - 1);
        const int cmax = min(min(max(__float2int_rd(gmaxc), 0), RES - 1) + 1, RES - 1);
        const int rmin = min(max(__float2int_rd(gminr), 0), RES - 1);
        const int rmax = min(min(max(__float2int_rd(gmaxr), 0), RES - 1) + 1, RES - 1);
        if (row < rmin || row > rmax || col0 > cmax || col0 + 63 < cmin) return;
    }

    __shared__ float tile[RANK][67];  // cols 0..64 used; 67 avoids bank conflicts
    const float* __restrict__ src = (plane == 0) ? gxy : (plane == 1) ? gxz : gyz;

    const int t = threadIdx.x;

    // Load 32 ranks x 64 cols, coalesced
#pragma unroll
    for (int i = 0; i < 8; i++) {
        const int idx = t + i * 256;
        const int r = idx >> 6;
        const int c = idx & 63;
        tile[r][c] = src[(size_t)r * CELLS + c0 + c];
    }
    // 65th column (x+1 of last cell), clamped at row edge
    if (t < RANK) {
        const int srccol = (col0 + 64 <= RES - 1) ? (c0 + 64) : (c0 + 63);
        tile[t][64] = src[(size_t)t * CELLS + srccol];
    }
    __syncthreads();

    // Write: thread t -> cell (t>>2), quad j = t&3 covers ranks 8j..8j+7 (16 B)
    {
        const int cell = t >> 2;
        const int j = t & 3;
        const int xg = col0 + cell;
        const int nb = (xg < RES - 1) ? cell + 1 : cell;  // x+1 clamp
        uint4 w;
        unsigned int* wp = &w.x;
#pragma unroll
        for (int k = 0; k < 4; k++) {
            const int r0 = 8 * j + 2 * k;
            const unsigned int b0 = enc_e5m2(tile[r0][cell]);
            const unsigned int b1 = enc_e5m2(tile[r0][nb]);
            const unsigned int b2 = enc_e5m2(tile[r0 + 1][cell]);
            const unsigned int b3 = enc_e5m2(tile[r0 + 1][nb]);
            wp[k] = b0 | (b1 << 8) | (b2 << 16) | (b3 << 24);
        }
        *reinterpret_cast<uint4*>(&g_tp[plane][((size_t)(c0 + cell) << 6) + (j << 4)]) = w;
    }
}

// ---------------------------------------------------------------------------
// Kernel 3: triplane sample. 4 lanes/point (8 points/warp); lane j = ranks 8j..8j+7.
// Decode groups RANK-pairs at fixed x: x1-pair = 1 AND, x0-pair = 1 PRMT.
// Full bilinear per 2 ranks = MUL + 3 FMA with broadcast weights: result is
// already (s_r, s_{r+1}) -> NO horizontal sums anywhere.
// ---------------------------------------------------------------------------
struct Corners {
    unsigned int o0, o1;   // byte offsets of (y0,x0) and (y1,x0) entries
    float wx, wy;
};

__device__ __forceinline__ Corners make_corners(float cx, float cy) {
    const float gx = ((cx + 1.0f) * 0.5f) * (float)(RES - 1);
    const float gy = ((cy + 1.0f) * 0.5f) * (float)(RES - 1);
    Corners c;
    c.wx = gx - floorf(gx);
    c.wy = gy - floorf(gy);
    const int x0 = min(max(__float2int_rd(gx), 0), RES - 1);
    const int y0 = min(max(__float2int_rd(gy), 0), RES - 1);
    const int dy = (min(y0 + 1, RES - 1) - y0) << 15;  // row stride = 512*64 B
    c.o0 = (unsigned int)(((y0 << 9) + x0) << 6);
    c.o1 = c.o0 + dy;
    return c;
}

__device__ __forceinline__ __half2 as_h2(unsigned int u) {
    return *reinterpret_cast<__half2*>(&u);
}

// s2[k] = bilinear samples of ranks (8j+2k, 8j+2k+1), fully interpolated.
__device__ __forceinline__ void plane_sample(const uint4& E, const uint4& F,
                                             __half2 w00, __half2 w01,
                                             __half2 w10, __half2 w11,
                                             __half2 s2[4]) {
    const unsigned int* e = &E.x;
    const unsigned int* f = &F.x;
#pragma unroll
    for (int k = 0; k < 4; k++) {
        const unsigned int ex0 = __byte_perm(e[k], 0, 0x2404);  // (r@x0, r+1@x0)
        const unsigned int ex1 = e[k] & 0xFF00FF00u;            // (r@x1, r+1@x1)
        const unsigned int fx0 = __byte_perm(f[k], 0, 0x2404);
        const unsigned int fx1 = f[k] & 0xFF00FF00u;
        __half2 s = __hmul2(as_h2(ex0), w00);
        s = __hfma2(as_h2(ex1), w01, s);
        s = __hfma2(as_h2(fx0), w10, s);
        s2[k] = __hfma2(as_h2(fx1), w11, s);
    }
}

__global__ void __launch_bounds__(256) sample_kernel(const float* __restrict__ pts,
                                                     const float* __restrict__ aabb,
                                                     float* __restrict__ out) {
    const int tid = blockIdx.x * blockDim.x + threadIdx.x;
    const int j = tid & 3;             // rank octet 0..3 (8 ranks each)
    const int point = tid >> 2;        // 4 lanes per point

    const float px = __ldg(&pts[point * 3 + 0]);
    const float py = __ldg(&pts[point * 3 + 1]);
    const float pz = __ldg(&pts[point * 3 + 2]);

    const float a0x = __ldg(&aabb[0]), a0y = __ldg(&aabb[1]), a0z = __ldg(&aabb[2]);
    const float a1x = __ldg(&aabb[3]), a1y = __ldg(&aabb[4]), a1z = __ldg(&aabb[5]);

    const float nx = (px - a0x) * (2.0f / (a1x - a0x)) - 1.0f;
    const float ny = (py - a0y) * (2.0f / (a1y - a0y)) - 1.0f;
    const float nz = (pz - a0z) * (2.0f / (a1z - a0z)) - 1.0f;

    const Corners cxy = make_corners(nx, ny);
    const Corners cxz = make_corners(nx, nz);
    const Corners cyz = make_corners(ny, nz);

    const char* __restrict__ P0 = reinterpret_cast<const char*>(g_tp[0]);
    const char* __restrict__ P1 = reinterpret_cast<const char*>(g_tp[1]);
    const char* __restrict__ P2 = reinterpret_cast<const char*>(g_tp[2]);
    const unsigned int lo = (unsigned int)j << 4;

    // 6 loads; each covers a full 64 B cell entry across the 4-lane group
    const uint4 E0 = *reinterpret_cast<const uint4*>(P0 + cxy.o0 + lo);
    const uint4 F0 = *reinterpret_cast<const uint4*>(P0 + cxy.o1 + lo);
    const uint4 E1 = *reinterpret_cast<const uint4*>(P1 + cxz.o0 + lo);
    const uint4 F1 = *reinterpret_cast<const uint4*>(P1 + cxz.o1 + lo);
    const uint4 E2 = *reinterpret_cast<const uint4*>(P2 + cyz.o0 + lo);
    const uint4 F2 = *reinterpret_cast<const uint4*>(P2 + cyz.o1 + lo);

    // Broadcast bilinear weights per plane
    const __half2 w00_0 = __float2half2_rn((1.0f - cxy.wx) * (1.0f - cxy.wy));
    const __half2 w01_0 = __float2half2_rn(cxy.wx * (1.0f - cxy.wy));
    const __half2 w10_0 = __float2half2_rn((1.0f - cxy.wx) * cxy.wy);
    const __half2 w11_0 = __float2half2_rn(cxy.wx * cxy.wy);
    const __half2 w00_1 = __float2half2_rn((1.0f - cxz.wx) * (1.0f - cxz.wy));
    const __half2 w01_1 = __float2half2_rn(cxz.wx * (1.0f - cxz.wy));
    const __half2 w10_1 = __float2half2_rn((1.0f - cxz.wx) * cxz.wy);
    const __half2 w11_1 = __float2half2_rn(cxz.wx * cxz.wy);
    const __half2 w00_2 = __float2half2_rn((1.0f - cyz.wx) * (1.0f - cyz.wy));
    const __half2 w01_2 = __float2half2_rn(cyz.wx * (1.0f - cyz.wy));
    const __half2 w10_2 = __float2half2_rn((1.0f - cyz.wx) * cyz.wy);
    const __half2 w11_2 = __float2half2_rn(cyz.wx * cyz.wy);

    __half2 sA[4], sB[4], sC[4];
    plane_sample(E0, F0, w00_0, w01_0, w10_0, w11_0, sA);
    plane_sample(E1, F1, w00_1, w01_1, w10_1, w11_1, sB);
    plane_sample(E2, F2, w00_2, w01_2, w10_2, w11_2, sC);

    // Triple product + accumulate, 2 ranks per op
    __half2 acc = __hmul2(__hmul2(sA[0], sB[0]), sC[0]);
#pragma unroll
    for (int k = 1; k < 4; k++) {
        acc = __hfma2(__hmul2(sA[k], sB[k]), sC[k], acc);
    }
    float sum = __low2float(acc) + __high2float(acc);

    // Reduce across the 4-lane group
    sum += __shfl_xor_sync(0xffffffffu, sum, 1, 4);
    sum += __shfl_xor_sync(0xffffffffu, sum, 2, 4);

    if (j == 0) {
        out[point] = expf(sum * (1.0f / (float)RANK));
    }
}

extern "C" void kernel_launch(void* const* d_in, const int* in_sizes, int n_in,
                              void* d_out, int out_size) {
    const float* pts  = (const float*)d_in[0];
    const float* gxy  = (const float*)d_in[1];
    const float* gxz  = (const float*)d_in[2];
    const float* gyz  = (const float*)d_in[3];
    const float* aabb = (const float*)d_in[4];
    float* out = (float*)d_out;

    init_kernel<<<1, 32>>>();
    bbox_kernel<<<384, 256>>>(pts);
    transpose_kernel<<<dim3(CELLS / 64, 3), 256>>>(gxy, gxz, gyz, aabb);

    // 4 lanes/point -> 64 points per 256-thread block
    sample_kernel<<<N_POINTS / 64, 256>>>(pts, aabb, out);
}

// round 9
// speedup vs baseline: 1.5927x; 1.0677x over previous
#include <cuda_runtime.h>
#include <cuda_fp16.h>

#define RES 512
#define RANK 32
#define CELLS (RES * RES)
#define N_POINTS (8192 * 128)

// e5m2 dup-pair layout: per plane, per cell (y,x): 64 bytes.
// Word k of 16B group j holds bytes [r@x0, r@x1, r+1@x0, r+1@x1], r = 8j+2k.
// e5m2 byte b decodes EXACTLY to the fp16 with bits (b << 8).
__device__ unsigned char g_tp[3][(size_t)CELLS * 2 * RANK];

// Encoded per-dim bbox of raw pts: [min_x,min_y,min_z, max_x,max_y,max_z]
__device__ unsigned int g_bbox[6];

__device__ __forceinline__ unsigned int encodeF(float f) {
    unsigned int b = __float_as_uint(f);
    return (b & 0x80000000u) ? ~b : (b | 0x80000000u);
}
__device__ __forceinline__ float decodeF(unsigned int u) {
    return (u & 0x80000000u) ? __uint_as_float(u ^ 0x80000000u)
                             : __uint_as_float(~u);
}

// f32 -> e5m2 byte, round-to-nearest via fp16 + mantissa-rounding add.
__device__ __forceinline__ unsigned int enc_e5m2(float v) {
    const unsigned int u = (unsigned int)__half_as_ushort(__float2half_rn(v));
    return ((u + 0x80u) >> 8) & 0xFFu;
}

// ---------------------------------------------------------------------------
// Kernel 0: reset bbox accumulators
// ---------------------------------------------------------------------------
__global__ void init_kernel() {
    int t = threadIdx.x;
    if (t < 3) g_bbox[t] = 0xFFFFFFFFu;
    else if (t < 6) g_bbox[t] = 0u;
}

// ---------------------------------------------------------------------------
// Kernel 1: per-dimension min/max of raw pts. float4 group-of-3 scheme:
// each group = 3 float4 = 12 floats = 4 points, fixed dim pattern:
//   f4[0] = (x,y,z,x)  f4[1] = (y,z,x,y)  f4[2] = (z,x,y,z)
// ---------------------------------------------------------------------------
__global__ void __launch_bounds__(256) bbox_kernel(const float4* __restrict__ pts4) {
    const int t = blockIdx.x * 256 + threadIdx.x;        // 65536 threads
    const int NGROUPS = (N_POINTS * 3) / 12;             // 262144
    float mnx = 3.0e38f, mny = 3.0e38f, mnz = 3.0e38f;
    float mxx = -3.0e38f, mxy = -3.0e38f, mxz = -3.0e38f;
#pragma unroll
    for (int i = 0; i < 4; i++) {
        const int g = t + i * 65536;
        if (g < NGROUPS) {
            const float4 a = __ldg(&pts4[3 * g + 0]);
            const float4 b = __ldg(&pts4[3 * g + 1]);
            const float4 c = __ldg(&pts4[3 * g + 2]);
            mnx = fminf(mnx, fminf(fminf(a.x, a.w), fminf(b.z, c.y)));
            mxx = fmaxf(mxx, fmaxf(fmaxf(a.x, a.w), fmaxf(b.z, c.y)));
            mny = fminf(mny, fminf(fminf(a.y, b.x), fminf(b.w, c.z)));
            mxy = fmaxf(mxy, fmaxf(fmaxf(a.y, b.x), fmaxf(b.w, c.z)));
            mnz = fminf(mnz, fminf(fminf(a.z, b.y), fminf(c.x, c.w)));
            mxz = fmaxf(mxz, fmaxf(fmaxf(a.z, b.y), fmaxf(c.x, c.w)));
        }
    }
    __shared__ unsigned int smn[3], smx[3];
    if (threadIdx.x < 3) { smn[threadIdx.x] = 0xFFFFFFFFu; smx[threadIdx.x] = 0u; }
    __syncthreads();
    atomicMin(&smn[0], encodeF(mnx));
    atomicMin(&smn[1], encodeF(mny));
    atomicMin(&smn[2], encodeF(mnz));
    atomicMax(&smx[0], encodeF(mxx));
    atomicMax(&smx[1], encodeF(mxy));
    atomicMax(&smx[2], encodeF(mxz));
    __syncthreads();
    if (threadIdx.x < 3) {
        atomicMin(&g_bbox[threadIdx.x], smn[threadIdx.x]);
        atomicMax(&g_bbox[3 + threadIdx.x], smx[threadIdx.x]);
    }
}

// ---------------------------------------------------------------------------
// Kernel 2: [RANK,H,W] f32 -> e5m2 dup-pair layout, bbox-gated.
// Block = 64 consecutive cells of one row x all 32 ranks.
// ---------------------------------------------------------------------------
__global__ void __launch_bounds__(256) transpose_kernel(const float* __restrict__ gxy,
                                                        const float* __restrict__ gxz,
                                                        const float* __restrict__ gyz,
                                                        const float* __restrict__ aabb) {
    const int plane = blockIdx.y;
    const int c0 = blockIdx.x * 64;
    const int row = c0 >> 9;
    const int col0 = c0 & (RES - 1);

    const int cdim = (plane == 2) ? 1 : 0;
    const int rdim = (plane == 0) ? 1 : 2;

    {   // bbox gate
        const float a0c = aabb[cdim], sc = (float)(RES - 1) / (aabb[3 + cdim] - aabb[cdim]);
        const float a0r = aabb[rdim], sr = (float)(RES - 1) / (aabb[3 + rdim] - aabb[rdim]);
        const float gminc = (decodeF(g_bbox[cdim]) - a0c) * sc;
        const float gmaxc = (decodeF(g_bbox[3 + cdim]) - a0c) * sc;
        const float gminr = (decodeF(g_bbox[rdim]) - a0r) * sr;
        const float gmaxr = (decodeF(g_bbox[3 + rdim]) - a0r) * sr;
        const int cmin = min(max(__float2int_rd(gminc), 0), RES - 1);
        const int cmax = min(min(max(__float2int_rd(gmaxc), 0), RES - 1) + 1, RES - 1);
        const int rmin = min(max(__float2int_rd(gminr), 0), RES - 1);
        const int rmax = min(min(max(__float2int_rd(gmaxr), 0), RES - 1) + 1, RES - 1);
        if (row < rmin || row > rmax || col0 > cmax || col0 + 63 < cmin) return;
    }

    __shared__ float tile[RANK][67];  // cols 0..64 used; 67 avoids bank conflicts
    const float* __restrict__ src = (plane == 0) ? gxy : (plane == 1) ? gxz : gyz;

    const int t = threadIdx.x;

    // Load 32 ranks x 64 cols via float4 (c0*4B is 256B-aligned)
#pragma unroll
    for (int i = 0; i < 2; i++) {
        const int q = t + i * 256;        // 0..511
        const int r = q >> 4;             // rank
        const int c4 = (q & 15) << 2;     // col start
        const float4 v = *reinterpret_cast<const float4*>(&src[(size_t)r * CELLS + c0 + c4]);
        tile[r][c4 + 0] = v.x;
        tile[r][c4 + 1] = v.y;
        tile[r][c4 + 2] = v.z;
        tile[r][c4 + 3] = v.w;
    }
    // 65th column (x+1 of last cell), clamped at row edge
    if (t < RANK) {
        const int srccol = (col0 + 64 <= RES - 1) ? (c0 + 64) : (c0 + 63);
        tile[t][64] = src[(size_t)t * CELLS + srccol];
    }
    __syncthreads();

    // Write: thread t -> cell (t>>2), quad j = t&3 covers ranks 8j..8j+7 (16 B)
    {
        const int cell = t >> 2;
        const int j = t & 3;
        const int xg = col0 + cell;
        const int nb = (xg < RES - 1) ? cell + 1 : cell;  // x+1 clamp
        uint4 w;
        unsigned int* wp = &w.x;
#pragma unroll
        for (int k = 0; k < 4; k++) {
            const int r0 = 8 * j + 2 * k;
            const unsigned int b0 = enc_e5m2(tile[r0][cell]);
            const unsigned int b1 = enc_e5m2(tile[r0][nb]);
            const unsigned int b2 = enc_e5m2(tile[r0 + 1][cell]);
            const unsigned int b3 = enc_e5m2(tile[r0 + 1][nb]);
            wp[k] = b0 | (b1 << 8) | (b2 << 16) | (b3 << 24);
        }
        *reinterpret_cast<uint4*>(&g_tp[plane][((size_t)(c0 + cell) << 6) + (j << 4)]) = w;
    }
}

// ---------------------------------------------------------------------------
// Kernel 3: triplane sample. 4 lanes/point (8 points/warp); lane j = ranks 8j..8j+7.
// ---------------------------------------------------------------------------
struct Corners {
    unsigned int o0, o1;   // byte offsets of (y0,x0) and (y1,x0) entries
    float wx, wy;
};

// gx/gy are final grid coords (already scaled to [0, RES-1] domain).
__device__ __forceinline__ Corners make_corners(float gx, float gy) {
    Corners c;
    c.wx = gx - floorf(gx);
    c.wy = gy - floorf(gy);
    const int x0 = min(max(__float2int_rd(gx), 0), RES - 1);
    const int y0 = min(max(__float2int_rd(gy), 0), RES - 1);
    const int dy = (min(y0 + 1, RES - 1) - y0) << 15;  // row stride = 512*64 B
    c.o0 = (unsigned int)(((y0 << 9) + x0) << 6);
    c.o1 = c.o0 + dy;
    return c;
}

__device__ __forceinline__ __half2 as_h2(unsigned int u) {
    return *reinterpret_cast<__half2*>(&u);
}

// s2[k] = bilinear samples of ranks (8j+2k, 8j+2k+1), fully interpolated.
__device__ __forceinline__ void plane_sample(const uint4& E, const uint4& F,
                                             __half2 w00, __half2 w01,
                                             __half2 w10, __half2 w11,
                                             __half2 s2[4]) {
    const unsigned int* e = &E.x;
    const unsigned int* f = &F.x;
#pragma unroll
    for (int k = 0; k < 4; k++) {
        const unsigned int ex0 = __byte_perm(e[k], 0, 0x2404);  // (r@x0, r+1@x0)
        const unsigned int ex1 = e[k] & 0xFF00FF00u;            // (r@x1, r+1@x1)
        const unsigned int fx0 = __byte_perm(f[k], 0, 0x2404);
        const unsigned int fx1 = f[k] & 0xFF00FF00u;
        __half2 s = __hmul2(as_h2(ex0), w00);
        s = __hfma2(as_h2(ex1), w01, s);
        s = __hfma2(as_h2(fx0), w10, s);
        s2[k] = __hfma2(as_h2(fx1), w11, s);
    }
}

__global__ void __launch_bounds__(256) sample_kernel(const float* __restrict__ pts,
                                                     const float* __restrict__ aabb,
                                                     float* __restrict__ out) {
    const int tid = blockIdx.x * blockDim.x + threadIdx.x;
    const int j = tid & 3;             // rank octet 0..3 (8 ranks each)
    const int point = tid >> 2;        // 4 lanes per point

    const float px = __ldg(&pts[point * 3 + 0]);
    const float py = __ldg(&pts[point * 3 + 1]);
    const float pz = __ldg(&pts[point * 3 + 2]);

    const float a0x = __ldg(&aabb[0]), a0y = __ldg(&aabb[1]), a0z = __ldg(&aabb[2]);
    const float a1x = __ldg(&aabb[3]), a1y = __ldg(&aabb[4]), a1z = __ldg(&aabb[5]);

    // Fused map: g = (p - a0) * ((RES-1)/(a1 - a0)), fast reciprocal.
    const float kx = __fdividef((float)(RES - 1), a1x - a0x);
    const float ky = __fdividef((float)(RES - 1), a1y - a0y);
    const float kz = __fdividef((float)(RES - 1), a1z - a0z);
    const float gxc = (px - a0x) * kx;
    const float gyc = (py - a0y) * ky;
    const float gzc = (pz - a0z) * kz;

    const Corners cxy = make_corners(gxc, gyc);
    const Corners cxz = make_corners(gxc, gzc);
    const Corners cyz = make_corners(gyc, gzc);

    const char* __restrict__ P0 = reinterpret_cast<const char*>(g_tp[0]);
    const char* __restrict__ P1 = reinterpret_cast<const char*>(g_tp[1]);
    const char* __restrict__ P2 = reinterpret_cast<const char*>(g_tp[2]);
    const unsigned int lo = (unsigned int)j << 4;

    // 6 loads; each covers a full 64 B cell entry across the 4-lane group
    const uint4 E0 = *reinterpret_cast<const uint4*>(P0 + cxy.o0 + lo);
    const uint4 F0 = *reinterpret_cast<const uint4*>(P0 + cxy.o1 + lo);
    const uint4 E1 = *reinterpret_cast<const uint4*>(P1 + cxz.o0 + lo);
    const uint4 F1 = *reinterpret_cast<const uint4*>(P1 + cxz.o1 + lo);
    const uint4 E2 = *reinterpret_cast<const uint4*>(P2 + cyz.o0 + lo);
    const uint4 F2 = *reinterpret_cast<const uint4*>(P2 + cyz.o1 + lo);

    // Broadcast bilinear weights per plane
    const float ox0 = 1.0f - cxy.wx, oy0 = 1.0f - cxy.wy;
    const float ox1 = 1.0f - cxz.wx, oy1 = 1.0f - cxz.wy;
    const float ox2 = 1.0f - cyz.wx, oy2 = 1.0f - cyz.wy;
    const __half2 w00_0 = __float2half2_rn(ox0 * oy0);
    const __half2 w01_0 = __float2half2_rn(cxy.wx * oy0);
    const __half2 w10_0 = __float2half2_rn(ox0 * cxy.wy);
    const __half2 w11_0 = __float2half2_rn(cxy.wx * cxy.wy);
    const __half2 w00_1 = __float2half2_rn(ox1 * oy1);
    const __half2 w01_1 = __float2half2_rn(cxz.wx * oy1);
    const __half2 w10_1 = __float2half2_rn(ox1 * cxz.wy);
    const __half2 w11_1 = __float2half2_rn(cxz.wx * cxz.wy);
    const __half2 w00_2 = __float2half2_rn(ox2 * oy2);
    const __half2 w01_2 = __float2half2_rn(cyz.wx * oy2);
    const __half2 w10_2 = __float2half2_rn(ox2 * cyz.wy);
    const __half2 w11_2 = __float2half2_rn(cyz.wx * cyz.wy);

    __half2 sA[4], sB[4], sC[4];
    plane_sample(E0, F0, w00_0, w01_0, w10_0, w11_0, sA);
    plane_sample(E1, F1, w00_1, w01_1, w10_1, w11_1, sB);
    plane_sample(E2, F2, w00_2, w01_2, w10_2, w11_2, sC);

    // Triple product + accumulate, 2 ranks per op
    __half2 acc = __hmul2(__hmul2(sA[0], sB[0]), sC[0]);
#pragma unroll
    for (int k = 1; k < 4; k++) {
        acc = __hfma2(__hmul2(sA[k], sB[k]), sC[k], acc);
    }
    float sum = __low2float(acc) + __high2float(acc);

    // Reduce across the 4-lane group
    sum += __shfl_xor_sync(0xffffffffu, sum, 1, 4);
    sum += __shfl_xor_sync(0xffffffffu, sum, 2, 4);

    if (j == 0) {
        out[point] = __expf(sum * (1.0f / (float)RANK));
    }
}

extern "C" void kernel_launch(void* const* d_in, const int* in_sizes, int n_in,
                              void* d_out, int out_size) {
    const float* pts  = (const float*)d_in[0];
    const float* gxy  = (const float*)d_in[1];
    const float* gxz  = (const float*)d_in[2];
    const float* gyz  = (const float*)d_in[3];
    const float* aabb = (const float*)d_in[4];
    float* out = (float*)d_out;

    init_kernel<<<1, 32>>>();
    bbox_kernel<<<256, 256>>>((const float4*)pts);
    transpose_kernel<<<dim3(CELLS / 64, 3), 256>>>(gxy, gxz, gyz, aabb);

    // 4 lanes/point -> 64 points per 256-thread block
    sample_kernel<<<N_POINTS / 64, 256>>>(pts, aabb, out);
}

// round 10
// speedup vs baseline: 1.6009x; 1.0052x over previous
#include <cuda_runtime.h>
#include <cuda_fp16.h>

#define RES 512
#define RANK 32
#define CELLS (RES * RES)
#define N_POINTS (8192 * 128)

// e5m2 dup-pair layout: per plane, per cell (y,x): 64 bytes.
// Word k of 16B group j holds bytes [r@x0, r@x1, r+1@x0, r+1@x1], r = 8j+2k.
// e5m2 byte b decodes EXACTLY to the fp16 with bits (b << 8).
__device__ unsigned char g_tp[3][(size_t)CELLS * 2 * RANK];

// Encoded per-dim bbox of raw pts: [min_x,min_y,min_z, max_x,max_y,max_z]
__device__ unsigned int g_bbox[6];

__device__ __forceinline__ unsigned int encodeF(float f) {
    unsigned int b = __float_as_uint(f);
    return (b & 0x80000000u) ? ~b : (b | 0x80000000u);
}
__device__ __forceinline__ float decodeF(unsigned int u) {
    return (u & 0x80000000u) ? __uint_as_float(u ^ 0x80000000u)
                             : __uint_as_float(~u);
}

// f32 -> e5m2 byte, round-to-nearest via fp16 + mantissa-rounding add.
__device__ __forceinline__ unsigned int enc_e5m2(float v) {
    const unsigned int u = (unsigned int)__half_as_ushort(__float2half_rn(v));
    return ((u + 0x80u) >> 8) & 0xFFu;
}

// ---------------------------------------------------------------------------
// Kernel 0: reset bbox accumulators
// ---------------------------------------------------------------------------
__global__ void init_kernel() {
    int t = threadIdx.x;
    if (t < 3) g_bbox[t] = 0xFFFFFFFFu;
    else if (t < 6) g_bbox[t] = 0u;
}

// ---------------------------------------------------------------------------
// Kernel 1: per-dimension min/max of raw pts. float4 group-of-3 scheme.
// ---------------------------------------------------------------------------
__global__ void __launch_bounds__(256) bbox_kernel(const float4* __restrict__ pts4) {
    const int t = blockIdx.x * 256 + threadIdx.x;        // 65536 threads
    const int NGROUPS = (N_POINTS * 3) / 12;             // 262144
    float mnx = 3.0e38f, mny = 3.0e38f, mnz = 3.0e38f;
    float mxx = -3.0e38f, mxy = -3.0e38f, mxz = -3.0e38f;
#pragma unroll
    for (int i = 0; i < 4; i++) {
        const int g = t + i * 65536;
        if (g < NGROUPS) {
            const float4 a = __ldg(&pts4[3 * g + 0]);
            const float4 b = __ldg(&pts4[3 * g + 1]);
            const float4 c = __ldg(&pts4[3 * g + 2]);
            mnx = fminf(mnx, fminf(fminf(a.x, a.w), fminf(b.z, c.y)));
            mxx = fmaxf(mxx, fmaxf(fmaxf(a.x, a.w), fmaxf(b.z, c.y)));
            mny = fminf(mny, fminf(fminf(a.y, b.x), fminf(b.w, c.z)));
            mxy = fmaxf(mxy, fmaxf(fmaxf(a.y, b.x), fmaxf(b.w, c.z)));
            mnz = fminf(mnz, fminf(fminf(a.z, b.y), fminf(c.x, c.w)));
            mxz = fmaxf(mxz, fmaxf(fmaxf(a.z, b.y), fmaxf(c.x, c.w)));
        }
    }
    __shared__ unsigned int smn[3], smx[3];
    if (threadIdx.x < 3) { smn[threadIdx.x] = 0xFFFFFFFFu; smx[threadIdx.x] = 0u; }
    __syncthreads();
    atomicMin(&smn[0], encodeF(mnx));
    atomicMin(&smn[1], encodeF(mny));
    atomicMin(&smn[2], encodeF(mnz));
    atomicMax(&smx[0], encodeF(mxx));
    atomicMax(&smx[1], encodeF(mxy));
    atomicMax(&smx[2], encodeF(mxz));
    __syncthreads();
    if (threadIdx.x < 3) {
        atomicMin(&g_bbox[threadIdx.x], smn[threadIdx.x]);
        atomicMax(&g_bbox[3 + threadIdx.x], smx[threadIdx.x]);
    }
}

// ---------------------------------------------------------------------------
// Kernel 2: [RANK,H,W] f32 -> e5m2 dup-pair layout, bbox-gated.
// ---------------------------------------------------------------------------
__global__ void __launch_bounds__(256) transpose_kernel(const float* __restrict__ gxy,
                                                        const float* __restrict__ gxz,
                                                        const float* __restrict__ gyz,
                                                        const float* __restrict__ aabb) {
    const int plane = blockIdx.y;
    const int c0 = blockIdx.x * 64;
    const int row = c0 >> 9;
    const int col0 = c0 & (RES - 1);

    const int cdim = (plane == 2) ? 1 : 0;
    const int rdim = (plane == 0) ? 1 : 2;

    {   // bbox gate
        const float a0c = aabb[cdim], sc = (float)(RES - 1) / (aabb[3 + cdim] - aabb[cdim]);
        const float a0r = aabb[rdim], sr = (float)(RES - 1) / (aabb[3 + rdim] - aabb[rdim]);
        const float gminc = (decodeF(g_bbox[cdim]) - a0c) * sc;
        const float gmaxc = (decodeF(g_bbox[3 + cdim]) - a0c) * sc;
        const float gminr = (decodeF(g_bbox[rdim]) - a0r) * sr;
        const float gmaxr = (decodeF(g_bbox[3 + rdim]) - a0r) * sr;
        const int cmin = min(max(__float2int_rd(gminc), 0), RES - 1);
        const int cmax = min(min(max(__float2int_rd(gmaxc), 0), RES - 1) + 1, RES - 1);
        const int rmin = min(max(__float2int_rd(gminr), 0), RES - 1);
        const int rmax = min(min(max(__float2int_rd(gmaxr), 0), RES - 1) + 1, RES - 1);
        if (row < rmin || row > rmax || col0 > cmax || col0 + 63 < cmin) return;
    }

    __shared__ float tile[RANK][67];
    const float* __restrict__ src = (plane == 0) ? gxy : (plane == 1) ? gxz : gyz;

    const int t = threadIdx.x;

    // Load 32 ranks x 64 cols via float4
#pragma unroll
    for (int i = 0; i < 2; i++) {
        const int q = t + i * 256;
        const int r = q >> 4;
        const int c4 = (q & 15) << 2;
        const float4 v = *reinterpret_cast<const float4*>(&src[(size_t)r * CELLS + c0 + c4]);
        tile[r][c4 + 0] = v.x;
        tile[r][c4 + 1] = v.y;
        tile[r][c4 + 2] = v.z;
        tile[r][c4 + 3] = v.w;
    }
    if (t < RANK) {
        const int srccol = (col0 + 64 <= RES - 1) ? (c0 + 64) : (c0 + 63);
        tile[t][64] = src[(size_t)t * CELLS + srccol];
    }
    __syncthreads();

    {
        const int cell = t >> 2;
        const int j = t & 3;
        const int xg = col0 + cell;
        const int nb = (xg < RES - 1) ? cell + 1 : cell;
        uint4 w;
        unsigned int* wp = &w.x;
#pragma unroll
        for (int k = 0; k < 4; k++) {
            const int r0 = 8 * j + 2 * k;
            const unsigned int b0 = enc_e5m2(tile[r0][cell]);
            const unsigned int b1 = enc_e5m2(tile[r0][nb]);
            const unsigned int b2 = enc_e5m2(tile[r0 + 1][cell]);
            const unsigned int b3 = enc_e5m2(tile[r0 + 1][nb]);
            wp[k] = b0 | (b1 << 8) | (b2 << 16) | (b3 << 24);
        }
        *reinterpret_cast<uint4*>(&g_tp[plane][((size_t)(c0 + cell) << 6) + (j << 4)]) = w;
    }
}

// ---------------------------------------------------------------------------
// Kernel 3: triplane sample. 4 lanes/point; lane j = ranks 8j..8j+7.
// Lane-specialized head: lane j computes ONLY plane j's corners/weights
// (lane 3 duplicates plane 0); 12 width-4 shuffles broadcast the state.
// ---------------------------------------------------------------------------
__device__ __forceinline__ __half2 as_h2(unsigned int u) {
    return *reinterpret_cast<__half2*>(&u);
}

// s2[k] = bilinear samples of ranks (8j+2k, 8j+2k+1), fully interpolated.
__device__ __forceinline__ void plane_sample(const uint4& E, const uint4& F,
                                             __half2 w00, __half2 w01,
                                             __half2 w10, __half2 w11,
                                             __half2 s2[4]) {
    const unsigned int* e = &E.x;
    const unsigned int* f = &F.x;
#pragma unroll
    for (int k = 0; k < 4; k++) {
        const unsigned int ex0 = __byte_perm(e[k], 0, 0x2404);  // (r@x0, r+1@x0)
        const unsigned int ex1 = e[k] & 0xFF00FF00u;            // (r@x1, r+1@x1)
        const unsigned int fx0 = __byte_perm(f[k], 0, 0x2404);
        const unsigned int fx1 = f[k] & 0xFF00FF00u;
        __half2 s = __hmul2(as_h2(ex0), w00);
        s = __hfma2(as_h2(ex1), w01, s);
        s = __hfma2(as_h2(fx0), w10, s);
        s2[k] = __hfma2(as_h2(fx1), w11, s);
    }
}

__global__ void __launch_bounds__(256) sample_kernel(const float* __restrict__ pts,
                                                     const float* __restrict__ aabb,
                                                     float* __restrict__ out) {
    const int tid = blockIdx.x * blockDim.x + threadIdx.x;
    const int j = tid & 3;             // rank octet 0..3 (8 ranks each)
    const int point = tid >> 2;        // 4 lanes per point

    // ---- Producer role: this lane computes plane p's head state ----
    const int p = (j == 3) ? 0 : j;
    const int d1 = (p == 2) ? 1 : 0;          // plane column dim
    const int d2 = (p == 0) ? 1 : 2;          // plane row dim

    const float c1 = __ldg(&pts[point * 3 + d1]);
    const float c2 = __ldg(&pts[point * 3 + d2]);
    const float a01 = __ldg(&aabb[d1]),     a02 = __ldg(&aabb[d2]);
    const float a11 = __ldg(&aabb[3 + d1]), a12 = __ldg(&aabb[3 + d2]);

    const float gx = (c1 - a01) * __fdividef((float)(RES - 1), a11 - a01);
    const float gy = (c2 - a02) * __fdividef((float)(RES - 1), a12 - a02);

    const float wx = gx - floorf(gx);
    const float wy = gy - floorf(gy);
    const int x0 = min(max(__float2int_rd(gx), 0), RES - 1);
    const int y0 = min(max(__float2int_rd(gy), 0), RES - 1);
    const int dyo = (min(y0 + 1, RES - 1) - y0) << 15;      // row stride 512*64B
    const unsigned int my_o0 = (unsigned int)(((y0 << 9) + x0) << 6);
    const unsigned int my_o1 = my_o0 + dyo;

    const float ox = 1.0f - wx, oy = 1.0f - wy;
    __half2 hA = __floats2half2_rn(ox * oy, wx * oy);   // (w00, w01)
    __half2 hB = __floats2half2_rn(ox * wy, wx * wy);   // (w10, w11)
    const unsigned int my_wA = *reinterpret_cast<unsigned int*>(&hA);
    const unsigned int my_wB = *reinterpret_cast<unsigned int*>(&hB);

    // ---- Broadcast head state across the 4-lane group (12 shuffles) ----
    const unsigned int FULL = 0xffffffffu;
    const unsigned int o0_0 = __shfl_sync(FULL, my_o0, 0, 4);
    const unsigned int o1_0 = __shfl_sync(FULL, my_o1, 0, 4);
    const unsigned int wA_0 = __shfl_sync(FULL, my_wA, 0, 4);
    const unsigned int wB_0 = __shfl_sync(FULL, my_wB, 0, 4);
    const unsigned int o0_1 = __shfl_sync(FULL, my_o0, 1, 4);
    const unsigned int o1_1 = __shfl_sync(FULL, my_o1, 1, 4);
    const unsigned int wA_1 = __shfl_sync(FULL, my_wA, 1, 4);
    const unsigned int wB_1 = __shfl_sync(FULL, my_wB, 1, 4);
    const unsigned int o0_2 = __shfl_sync(FULL, my_o0, 2, 4);
    const unsigned int o1_2 = __shfl_sync(FULL, my_o1, 2, 4);
    const unsigned int wA_2 = __shfl_sync(FULL, my_wA, 2, 4);
    const unsigned int wB_2 = __shfl_sync(FULL, my_wB, 2, 4);

    const char* __restrict__ P0 = reinterpret_cast<const char*>(g_tp[0]);
    const char* __restrict__ P1 = reinterpret_cast<const char*>(g_tp[1]);
    const char* __restrict__ P2 = reinterpret_cast<const char*>(g_tp[2]);
    const unsigned int lo = (unsigned int)j << 4;

    // 6 loads; each covers a full 64 B cell entry across the 4-lane group
    const uint4 E0 = *reinterpret_cast<const uint4*>(P0 + o0_0 + lo);
    const uint4 F0 = *reinterpret_cast<const uint4*>(P0 + o1_0 + lo);
    const uint4 E1 = *reinterpret_cast<const uint4*>(P1 + o0_1 + lo);
    const uint4 F1 = *reinterpret_cast<const uint4*>(P1 + o1_1 + lo);
    const uint4 E2 = *reinterpret_cast<const uint4*>(P2 + o0_2 + lo);
    const uint4 F2 = *reinterpret_cast<const uint4*>(P2 + o1_2 + lo);

    // Expand packed weights to broadcast half2s (bit-identical to direct cvt)
    const __half2 w00_0 = as_h2(__byte_perm(wA_0, 0, 0x1010));
    const __half2 w01_0 = as_h2(__byte_perm(wA_0, 0, 0x3232));
    const __half2 w10_0 = as_h2(__byte_perm(wB_0, 0, 0x1010));
    const __half2 w11_0 = as_h2(__byte_perm(wB_0, 0, 0x3232));
    const __half2 w00_1 = as_h2(__byte_perm(wA_1, 0, 0x1010));
    const __half2 w01_1 = as_h2(__byte_perm(wA_1, 0, 0x3232));
    const __half2 w10_1 = as_h2(__byte_perm(wB_1, 0, 0x1010));
    const __half2 w11_1 = as_h2(__byte_perm(wB_1, 0, 0x3232));
    const __half2 w00_2 = as_h2(__byte_perm(wA_2, 0, 0x1010));
    const __half2 w01_2 = as_h2(__byte_perm(wA_2, 0, 0x3232));
    const __half2 w10_2 = as_h2(__byte_perm(wB_2, 0, 0x1010));
    const __half2 w11_2 = as_h2(__byte_perm(wB_2, 0, 0x3232));

    __half2 sA[4], sB[4], sC[4];
    plane_sample(E0, F0, w00_0, w01_0, w10_0, w11_0, sA);
    plane_sample(E1, F1, w00_1, w01_1, w10_1, w11_1, sB);
    plane_sample(E2, F2, w00_2, w01_2, w10_2, w11_2, sC);

    // Triple product + accumulate, 2 ranks per op
    __half2 acc = __hmul2(__hmul2(sA[0], sB[0]), sC[0]);
#pragma unroll
    for (int k = 1; k < 4; k++) {
        acc = __hfma2(__hmul2(sA[k], sB[k]), sC[k], acc);
    }
    float sum = __low2float(acc) + __high2float(acc);

    // Reduce across the 4-lane group
    sum += __shfl_xor_sync(FULL, sum, 1, 4);
    sum += __shfl_xor_sync(FULL, sum, 2, 4);

    if (j == 0) {
        out[point] = __expf(sum * (1.0f / (float)RANK));
    }
}

extern "C" void kernel_launch(void* const* d_in, const int* in_sizes, int n_in,
                              void* d_out, int out_size) {
    const float* pts  = (const float*)d_in[0];
    const float* gxy  = (const float*)d_in[1];
    const float* gxz  = (const float*)d_in[2];
    const float* gyz  = (const float*)d_in[3];
    const float* aabb = (const float*)d_in[4];
    float* out = (float*)d_out;

    init_kernel<<<1, 32>>>();
    bbox_kernel<<<256, 256>>>((const float4*)pts);
    transpose_kernel<<<dim3(CELLS / 64, 3), 256>>>(gxy, gxz, gyz, aabb);

    // 4 lanes/point -> 64 points per 256-thread block
    sample_kernel<<<N_POINTS / 64, 256>>>(pts, aabb, out);
}

// round 11
// speedup vs baseline: 1.6445x; 1.0273x over previous
#include <cuda_runtime.h>
#include <cuda_fp16.h>

#define RES 512
#define RANK 32
#define CELLS (RES * RES)
#define N_POINTS (8192 * 128)

// e5m2 dup-pair layout: per plane, per cell (y,x): 64 bytes.
// Word k of 16B group j holds bytes [r@x0, r@x1, r+1@x0, r+1@x1], r = 8j+2k.
// e5m2 byte b decodes EXACTLY to the fp16 with bits (b << 8).
__device__ unsigned char g_tp[3][(size_t)CELLS * 2 * RANK];

// Encoded per-dim bbox of raw pts: [min_x,min_y,min_z, max_x,max_y,max_z]
__device__ unsigned int g_bbox[6];

// Affine map: grid = p * g_map[0].{x,y,z} + g_map[1].{x,y,z}
__device__ float4 g_map[2];

__device__ __forceinline__ unsigned int encodeF(float f) {
    unsigned int b = __float_as_uint(f);
    return (b & 0x80000000u) ? ~b : (b | 0x80000000u);
}
__device__ __forceinline__ float decodeF(unsigned int u) {
    return (u & 0x80000000u) ? __uint_as_float(u ^ 0x80000000u)
                             : __uint_as_float(~u);
}

// f32 -> e5m2 byte, round-to-nearest via fp16 + mantissa-rounding add.
__device__ __forceinline__ unsigned int enc_e5m2(float v) {
    const unsigned int u = (unsigned int)__half_as_ushort(__float2half_rn(v));
    return ((u + 0x80u) >> 8) & 0xFFu;
}

// ---------------------------------------------------------------------------
// Kernel 0: reset bbox accumulators + precompute affine map
// ---------------------------------------------------------------------------
__global__ void init_kernel(const float* __restrict__ aabb) {
    int t = threadIdx.x;
    if (t < 3) g_bbox[t] = 0xFFFFFFFFu;
    else if (t < 6) g_bbox[t] = 0u;
    if (t == 0) {
        float k[3], o[3];
#pragma unroll
        for (int d = 0; d < 3; d++) {
            const float a0 = aabb[d], a1 = aabb[3 + d];
            k[d] = (float)(RES - 1) / (a1 - a0);
            o[d] = -a0 * k[d];
        }
        g_map[0] = make_float4(k[0], k[1], k[2], 0.0f);
        g_map[1] = make_float4(o[0], o[1], o[2], 0.0f);
    }
}

// ---------------------------------------------------------------------------
// Kernel 1: per-dimension min/max of raw pts. float4 group-of-3 scheme.
// ---------------------------------------------------------------------------
__global__ void __launch_bounds__(256) bbox_kernel(const float4* __restrict__ pts4) {
    const int t = blockIdx.x * 256 + threadIdx.x;        // 65536 threads
    const int NGROUPS = (N_POINTS * 3) / 12;             // 262144
    float mnx = 3.0e38f, mny = 3.0e38f, mnz = 3.0e38f;
    float mxx = -3.0e38f, mxy = -3.0e38f, mxz = -3.0e38f;
#pragma unroll
    for (int i = 0; i < 4; i++) {
        const int g = t + i * 65536;
        if (g < NGROUPS) {
            const float4 a = __ldg(&pts4[3 * g + 0]);
            const float4 b = __ldg(&pts4[3 * g + 1]);
            const float4 c = __ldg(&pts4[3 * g + 2]);
            mnx = fminf(mnx, fminf(fminf(a.x, a.w), fminf(b.z, c.y)));
            mxx = fmaxf(mxx, fmaxf(fmaxf(a.x, a.w), fmaxf(b.z, c.y)));
            mny = fminf(mny, fminf(fminf(a.y, b.x), fminf(b.w, c.z)));
            mxy = fmaxf(mxy, fmaxf(fmaxf(a.y, b.x), fmaxf(b.w, c.z)));
            mnz = fminf(mnz, fminf(fminf(a.z, b.y), fminf(c.x, c.w)));
            mxz = fmaxf(mxz, fmaxf(fmaxf(a.z, b.y), fmaxf(c.x, c.w)));
        }
    }
    __shared__ unsigned int smn[3], smx[3];
    if (threadIdx.x < 3) { smn[threadIdx.x] = 0xFFFFFFFFu; smx[threadIdx.x] = 0u; }
    __syncthreads();
    atomicMin(&smn[0], encodeF(mnx));
    atomicMin(&smn[1], encodeF(mny));
    atomicMin(&smn[2], encodeF(mnz));
    atomicMax(&smx[0], encodeF(mxx));
    atomicMax(&smx[1], encodeF(mxy));
    atomicMax(&smx[2], encodeF(mxz));
    __syncthreads();
    if (threadIdx.x < 3) {
        atomicMin(&g_bbox[threadIdx.x], smn[threadIdx.x]);
        atomicMax(&g_bbox[3 + threadIdx.x], smx[threadIdx.x]);
    }
}

// ---------------------------------------------------------------------------
// Kernel 2: [RANK,H,W] f32 -> e5m2 dup-pair layout, bbox-gated.
// ---------------------------------------------------------------------------
__global__ void __launch_bounds__(256) transpose_kernel(const float* __restrict__ gxy,
                                                        const float* __restrict__ gxz,
                                                        const float* __restrict__ gyz,
                                                        const float* __restrict__ aabb) {
    const int plane = blockIdx.y;
    const int c0 = blockIdx.x * 64;
    const int row = c0 >> 9;
    const int col0 = c0 & (RES - 1);

    const int cdim = (plane == 2) ? 1 : 0;
    const int rdim = (plane == 0) ? 1 : 2;

    {   // bbox gate
        const float a0c = aabb[cdim], sc = (float)(RES - 1) / (aabb[3 + cdim] - aabb[cdim]);
        const float a0r = aabb[rdim], sr = (float)(RES - 1) / (aabb[3 + rdim] - aabb[rdim]);
        const float gminc = (decodeF(g_bbox[cdim]) - a0c) * sc;
        const float gmaxc = (decodeF(g_bbox[3 + cdim]) - a0c) * sc;
        const float gminr = (decodeF(g_bbox[rdim]) - a0r) * sr;
        const float gmaxr = (decodeF(g_bbox[3 + rdim]) - a0r) * sr;
        const int cmin = min(max(__float2int_rd(gminc), 0), RES - 1);
        const int cmax = min(min(max(__float2int_rd(gmaxc), 0), RES - 1) + 1, RES - 1);
        const int rmin = min(max(__float2int_rd(gminr), 0), RES - 1);
        const int rmax = min(min(max(__float2int_rd(gmaxr), 0), RES - 1) + 1, RES - 1);
        if (row < rmin || row > rmax || col0 > cmax || col0 + 63 < cmin) return;
    }

    __shared__ float tile[RANK][67];
    const float* __restrict__ src = (plane == 0) ? gxy : (plane == 1) ? gxz : gyz;

    const int t = threadIdx.x;

    // Load 32 ranks x 64 cols via float4
#pragma unroll
    for (int i = 0; i < 2; i++) {
        const int q = t + i * 256;
        const int r = q >> 4;
        const int c4 = (q & 15) << 2;
        const float4 v = *reinterpret_cast<const float4*>(&src[(size_t)r * CELLS + c0 + c4]);
        tile[r][c4 + 0] = v.x;
        tile[r][c4 + 1] = v.y;
        tile[r][c4 + 2] = v.z;
        tile[r][c4 + 3] = v.w;
    }
    if (t < RANK) {
        const int srccol = (col0 + 64 <= RES - 1) ? (c0 + 64) : (c0 + 63);
        tile[t][64] = src[(size_t)t * CELLS + srccol];
    }
    __syncthreads();

    {
        const int cell = t >> 2;
        const int j = t & 3;
        const int xg = col0 + cell;
        const int nb = (xg < RES - 1) ? cell + 1 : cell;
        uint4 w;
        unsigned int* wp = &w.x;
#pragma unroll
        for (int k = 0; k < 4; k++) {
            const int r0 = 8 * j + 2 * k;
            const unsigned int b0 = enc_e5m2(tile[r0][cell]);
            const unsigned int b1 = enc_e5m2(tile[r0][nb]);
            const unsigned int b2 = enc_e5m2(tile[r0 + 1][cell]);
            const unsigned int b3 = enc_e5m2(tile[r0 + 1][nb]);
            wp[k] = b0 | (b1 << 8) | (b2 << 16) | (b3 << 24);
        }
        *reinterpret_cast<uint4*>(&g_tp[plane][((size_t)(c0 + cell) << 6) + (j << 4)]) = w;
    }
}

// ---------------------------------------------------------------------------
// Kernel 3: triplane sample. 4 lanes/point; lane j = ranks 8j..8j+7.
// ---------------------------------------------------------------------------
struct Corners {
    unsigned int o0, o1;   // byte offsets of (y0,x0) and (y1,x0) entries
    __half2 wx2, wy2;      // duplicated fractional weights
};

// gx/gy are final grid coords (already affinely mapped).
__device__ __forceinline__ Corners make_corners(float gx, float gy) {
    Corners c;
    c.wx2 = __float2half2_rn(gx - floorf(gx));
    c.wy2 = __float2half2_rn(gy - floorf(gy));
    const int x0 = min(max(__float2int_rd(gx), 0), RES - 1);
    const int y0 = min(max(__float2int_rd(gy), 0), RES - 1);
    const unsigned int dy = (y0 < RES - 1) ? 32768u : 0u;   // 512*64 B row stride
    c.o0 = (unsigned int)(((y0 << 9) + x0) << 6);
    c.o1 = c.o0 + dy;
    return c;
}

__device__ __forceinline__ __half2 as_h2(unsigned int u) {
    return *reinterpret_cast<__half2*>(&u);
}

// s2[k] = bilinear samples of ranks (8j+2k, 8j+2k+1), fully interpolated.
__device__ __forceinline__ void plane_sample(const uint4& E, const uint4& F,
                                             __half2 w00, __half2 w01,
                                             __half2 w10, __half2 w11,
                                             __half2 s2[4]) {
    const unsigned int* e = &E.x;
    const unsigned int* f = &F.x;
#pragma unroll
    for (int k = 0; k < 4; k++) {
        const unsigned int ex0 = __byte_perm(e[k], 0, 0x2404);  // (r@x0, r+1@x0)
        const unsigned int ex1 = e[k] & 0xFF00FF00u;            // (r@x1, r+1@x1)
        const unsigned int fx0 = __byte_perm(f[k], 0, 0x2404);
        const unsigned int fx1 = f[k] & 0xFF00FF00u;
        __half2 s = __hmul2(as_h2(ex0), w00);
        s = __hfma2(as_h2(ex1), w01, s);
        s = __hfma2(as_h2(fx0), w10, s);
        s2[k] = __hfma2(as_h2(fx1), w11, s);
    }
}

__global__ void __launch_bounds__(256) sample_kernel(const float* __restrict__ pts,
                                                     float* __restrict__ out) {
    const int tid = blockIdx.x * blockDim.x + threadIdx.x;
    const int j = tid & 3;             // rank octet 0..3 (8 ranks each)
    const int point = tid >> 2;        // 4 lanes per point

    const float px = __ldg(&pts[point * 3 + 0]);
    const float py = __ldg(&pts[point * 3 + 1]);
    const float pz = __ldg(&pts[point * 3 + 2]);

    const float4 K = g_map[0];
    const float4 O = g_map[1];
    const float gxc = fmaf(px, K.x, O.x);
    const float gyc = fmaf(py, K.y, O.y);
    const float gzc = fmaf(pz, K.z, O.z);

    const Corners cxy = make_corners(gxc, gyc);
    const Corners cxz = make_corners(gxc, gzc);
    const Corners cyz = make_corners(gyc, gzc);

    const char* __restrict__ P0 = reinterpret_cast<const char*>(g_tp[0]);
    const char* __restrict__ P1 = reinterpret_cast<const char*>(g_tp[1]);
    const char* __restrict__ P2 = reinterpret_cast<const char*>(g_tp[2]);
    const unsigned int lo = (unsigned int)j << 4;

    // 6 loads; each covers a full 64 B cell entry across the 4-lane group
    const uint4 E0 = *reinterpret_cast<const uint4*>(P0 + cxy.o0 + lo);
    const uint4 F0 = *reinterpret_cast<const uint4*>(P0 + cxy.o1 + lo);
    const uint4 E1 = *reinterpret_cast<const uint4*>(P1 + cxz.o0 + lo);
    const uint4 F1 = *reinterpret_cast<const uint4*>(P1 + cxz.o1 + lo);
    const uint4 E2 = *reinterpret_cast<const uint4*>(P2 + cyz.o0 + lo);
    const uint4 F2 = *reinterpret_cast<const uint4*>(P2 + cyz.o1 + lo);

    // Weights built in fp16: 2 HSUB2 + 4 HMUL2 per plane
    const __half2 ONE = __float2half2_rn(1.0f);
    const __half2 ox0 = __hsub2(ONE, cxy.wx2), oy0 = __hsub2(ONE, cxy.wy2);
    const __half2 ox1 = __hsub2(ONE, cxz.wx2), oy1 = __hsub2(ONE, cxz.wy2);
    const __half2 ox2 = __hsub2(ONE, cyz.wx2), oy2 = __hsub2(ONE, cyz.wy2);

    __half2 sA[4], sB[4], sC[4];
    plane_sample(E0, F0, __hmul2(ox0, oy0), __hmul2(cxy.wx2, oy0),
                 __hmul2(ox0, cxy.wy2), __hmul2(cxy.wx2, cxy.wy2), sA);
    plane_sample(E1, F1, __hmul2(ox1, oy1), __hmul2(cxz.wx2, oy1),
                 __hmul2(ox1, cxz.wy2), __hmul2(cxz.wx2, cxz.wy2), sB);
    plane_sample(E2, F2, __hmul2(ox2, oy2), __hmul2(cyz.wx2, oy2),
                 __hmul2(ox2, cyz.wy2), __hmul2(cyz.wx2, cyz.wy2), sC);

    // Triple product + accumulate, 2 ranks per op
    __half2 acc = __hmul2(__hmul2(sA[0], sB[0]), sC[0]);
#pragma unroll
    for (int k = 1; k < 4; k++) {
        acc = __hfma2(__hmul2(sA[k], sB[k]), sC[k], acc);
    }
    float sum = __low2float(acc) + __high2float(acc);

    // Reduce across the 4-lane group
    sum += __shfl_xor_sync(0xffffffffu, sum, 1, 4);
    sum += __shfl_xor_sync(0xffffffffu, sum, 2, 4);

    if (j == 0) {
        out[point] = __expf(sum * (1.0f / (float)RANK));
    }
}

extern "C" void kernel_launch(void* const* d_in, const int* in_sizes, int n_in,
                              void* d_out, int out_size) {
    const float* pts  = (const float*)d_in[0];
    const float* gxy  = (const float*)d_in[1];
    const float* gxz  = (const float*)d_in[2];
    const float* gyz  = (const float*)d_in[3];
    const float* aabb = (const float*)d_in[4];
    float* out = (float*)d_out;

    init_kernel<<<1, 32>>>(aabb);
    bbox_kernel<<<256, 256>>>((const float4*)pts);
    transpose_kernel<<<dim3(CELLS / 64, 3), 256>>>(gxy, gxz, gyz, aabb);

    // 4 lanes/point -> 64 points per 256-thread block
    sample_kernel<<<N_POINTS / 64, 256>>>(pts, out);
}

// round 12
// speedup vs baseline: 1.6465x; 1.0012x over previous
#include <cuda_runtime.h>
#include <cuda_fp16.h>

#define RES 512
#define RANK 32
#define CELLS (RES * RES)
#define N_POINTS (8192 * 128)

// e5m2 dup-pair layout: per plane, per cell (y,x): 64 bytes.
// Word k of 16B group j holds bytes [r@x0, r@x1, r+1@x0, r+1@x1], r = 8j+2k.
// e5m2 byte b decodes EXACTLY to the fp16 with bits (b << 8).
__device__ unsigned char g_tp[3][(size_t)CELLS * 2 * RANK];

// Encoded per-dim bbox of raw pts. Static init; graph replays are idempotent
// (atomicMin/Max of the same data over its own result is a fixed point).
__device__ unsigned int g_bbox[6] = {0xFFFFFFFFu, 0xFFFFFFFFu, 0xFFFFFFFFu, 0u, 0u, 0u};

// Affine map: grid = p * g_map[0].{x,y,z} + g_map[1].{x,y,z}
__device__ float4 g_map[2];

__device__ __forceinline__ unsigned int encodeF(float f) {
    unsigned int b = __float_as_uint(f);
    return (b & 0x80000000u) ? ~b : (b | 0x80000000u);
}
__device__ __forceinline__ float decodeF(unsigned int u) {
    return (u & 0x80000000u) ? __uint_as_float(u ^ 0x80000000u)
                             : __uint_as_float(~u);
}

// f32 -> e5m2 byte, round-to-nearest via fp16 + mantissa-rounding add.
__device__ __forceinline__ unsigned int enc_e5m2(float v) {
    const unsigned int u = (unsigned int)__half_as_ushort(__float2half_rn(v));
    return ((u + 0x80u) >> 8) & 0xFFu;
}

// ---------------------------------------------------------------------------
// Kernel 1: per-dimension min/max of raw pts + g_map compute (block 0).
// float4 group-of-3 scheme: 3 float4 = 4 points, fixed dim pattern.
// ---------------------------------------------------------------------------
__global__ void __launch_bounds__(256) bbox_kernel(const float4* __restrict__ pts4,
                                                   const float* __restrict__ aabb) {
    const int t = blockIdx.x * 256 + threadIdx.x;        // 65536 threads
    if (t == 0) {   // fold former init_kernel's g_map computation here
        float k[3], o[3];
#pragma unroll
        for (int d = 0; d < 3; d++) {
            const float a0 = aabb[d], a1 = aabb[3 + d];
            k[d] = (float)(RES - 1) / (a1 - a0);
            o[d] = -a0 * k[d];
        }
        g_map[0] = make_float4(k[0], k[1], k[2], 0.0f);
        g_map[1] = make_float4(o[0], o[1], o[2], 0.0f);
    }

    const int NGROUPS = (N_POINTS * 3) / 12;             // 262144
    float mnx = 3.0e38f, mny = 3.0e38f, mnz = 3.0e38f;
    float mxx = -3.0e38f, mxy = -3.0e38f, mxz = -3.0e38f;
#pragma unroll
    for (int i = 0; i < 4; i++) {
        const int g = t + i * 65536;
        if (g < NGROUPS) {
            const float4 a = __ldg(&pts4[3 * g + 0]);
            const float4 b = __ldg(&pts4[3 * g + 1]);
            const float4 c = __ldg(&pts4[3 * g + 2]);
            mnx = fminf(mnx, fminf(fminf(a.x, a.w), fminf(b.z, c.y)));
            mxx = fmaxf(mxx, fmaxf(fmaxf(a.x, a.w), fmaxf(b.z, c.y)));
            mny = fminf(mny, fminf(fminf(a.y, b.x), fminf(b.w, c.z)));
            mxy = fmaxf(mxy, fmaxf(fmaxf(a.y, b.x), fmaxf(b.w, c.z)));
            mnz = fminf(mnz, fminf(fminf(a.z, b.y), fminf(c.x, c.w)));
            mxz = fmaxf(mxz, fmaxf(fmaxf(a.z, b.y), fmaxf(c.x, c.w)));
        }
    }
    __shared__ unsigned int smn[3], smx[3];
    if (threadIdx.x < 3) { smn[threadIdx.x] = 0xFFFFFFFFu; smx[threadIdx.x] = 0u; }
    __syncthreads();
    atomicMin(&smn[0], encodeF(mnx));
    atomicMin(&smn[1], encodeF(mny));
    atomicMin(&smn[2], encodeF(mnz));
    atomicMax(&smx[0], encodeF(mxx));
    atomicMax(&smx[1], encodeF(mxy));
    atomicMax(&smx[2], encodeF(mxz));
    __syncthreads();
    if (threadIdx.x < 3) {
        atomicMin(&g_bbox[threadIdx.x], smn[threadIdx.x]);
        atomicMax(&g_bbox[3 + threadIdx.x], smx[threadIdx.x]);
    }
}

// ---------------------------------------------------------------------------
// Kernel 2: [RANK,H,W] f32 -> e5m2 dup-pair layout, bbox-gated.
// ---------------------------------------------------------------------------
__global__ void __launch_bounds__(256) transpose_kernel(const float* __restrict__ gxy,
                                                        const float* __restrict__ gxz,
                                                        const float* __restrict__ gyz,
                                                        const float* __restrict__ aabb) {
    const int plane = blockIdx.y;
    const int c0 = blockIdx.x * 64;
    const int row = c0 >> 9;
    const int col0 = c0 & (RES - 1);

    const int cdim = (plane == 2) ? 1 : 0;
    const int rdim = (plane == 0) ? 1 : 2;

    {   // bbox gate
        const float a0c = aabb[cdim], sc = (float)(RES - 1) / (aabb[3 + cdim] - aabb[cdim]);
        const float a0r = aabb[rdim], sr = (float)(RES - 1) / (aabb[3 + rdim] - aabb[rdim]);
        const float gminc = (decodeF(g_bbox[cdim]) - a0c) * sc;
        const float gmaxc = (decodeF(g_bbox[3 + cdim]) - a0c) * sc;
        const float gminr = (decodeF(g_bbox[rdim]) - a0r) * sr;
        const float gmaxr = (decodeF(g_bbox[3 + rdim]) - a0r) * sr;
        const int cmin = min(max(__float2int_rd(gminc), 0), RES - 1);
        const int cmax = min(min(max(__float2int_rd(gmaxc), 0), RES - 1) + 1, RES - 1);
        const int rmin = min(max(__float2int_rd(gminr), 0), RES - 1);
        const int rmax = min(min(max(__float2int_rd(gmaxr), 0), RES - 1) + 1, RES - 1);
        if (row < rmin || row > rmax || col0 > cmax || col0 + 63 < cmin) return;
    }

    __shared__ float tile[RANK][67];
    const float* __restrict__ src = (plane == 0) ? gxy : (plane == 1) ? gxz : gyz;

    const int t = threadIdx.x;

    // Load 32 ranks x 64 cols via float4
#pragma unroll
    for (int i = 0; i < 2; i++) {
        const int q = t + i * 256;
        const int r = q >> 4;
        const int c4 = (q & 15) << 2;
        const float4 v = *reinterpret_cast<const float4*>(&src[(size_t)r * CELLS + c0 + c4]);
        tile[r][c4 + 0] = v.x;
        tile[r][c4 + 1] = v.y;
        tile[r][c4 + 2] = v.z;
        tile[r][c4 + 3] = v.w;
    }
    if (t < RANK) {
        const int srccol = (col0 + 64 <= RES - 1) ? (c0 + 64) : (c0 + 63);
        tile[t][64] = src[(size_t)t * CELLS + srccol];
    }
    __syncthreads();

    {
        const int cell = t >> 2;
        const int j = t & 3;
        const int xg = col0 + cell;
        const int nb = (xg < RES - 1) ? cell + 1 : cell;
        uint4 w;
        unsigned int* wp = &w.x;
#pragma unroll
        for (int k = 0; k < 4; k++) {
            const int r0 = 8 * j + 2 * k;
            const unsigned int b0 = enc_e5m2(tile[r0][cell]);
            const unsigned int b1 = enc_e5m2(tile[r0][nb]);
            const unsigned int b2 = enc_e5m2(tile[r0 + 1][cell]);
            const unsigned int b3 = enc_e5m2(tile[r0 + 1][nb]);
            wp[k] = b0 | (b1 << 8) | (b2 << 16) | (b3 << 24);
        }
        *reinterpret_cast<uint4*>(&g_tp[plane][((size_t)(c0 + cell) << 6) + (j << 4)]) = w;
    }
}

// ---------------------------------------------------------------------------
// Kernel 3: triplane sample. 4 lanes/point; lane j = ranks 8j..8j+7.
// __launch_bounds__(256, 8): cap at 32 regs so 8 blocks (64 warps) fit per SM.
// ---------------------------------------------------------------------------
struct Corners {
    unsigned int o0, o1;   // byte offsets of (y0,x0) and (y1,x0) entries
    __half2 wx2, wy2;      // duplicated fractional weights
};

// gx/gy are final grid coords (already affinely mapped).
__device__ __forceinline__ Corners make_corners(float gx, float gy) {
    Corners c;
    c.wx2 = __float2half2_rn(gx - floorf(gx));
    c.wy2 = __float2half2_rn(gy - floorf(gy));
    const int x0 = min(max(__float2int_rd(gx), 0), RES - 1);
    const int y0 = min(max(__float2int_rd(gy), 0), RES - 1);
    const unsigned int dy = (y0 < RES - 1) ? 32768u : 0u;   // 512*64 B row stride
    c.o0 = (unsigned int)(((y0 << 9) + x0) << 6);
    c.o1 = c.o0 + dy;
    return c;
}

__device__ __forceinline__ __half2 as_h2(unsigned int u) {
    return *reinterpret_cast<__half2*>(&u);
}

// s2[k] = bilinear samples of ranks (8j+2k, 8j+2k+1), fully interpolated.
__device__ __forceinline__ void plane_sample(const uint4& E, const uint4& F,
                                             __half2 w00, __half2 w01,
                                             __half2 w10, __half2 w11,
                                             __half2 s2[4]) {
    const unsigned int* e = &E.x;
    const unsigned int* f = &F.x;
#pragma unroll
    for (int k = 0; k < 4; k++) {
        const unsigned int ex0 = __byte_perm(e[k], 0, 0x2404);  // (r@x0, r+1@x0)
        const unsigned int ex1 = e[k] & 0xFF00FF00u;            // (r@x1, r+1@x1)
        const unsigned int fx0 = __byte_perm(f[k], 0, 0x2404);
        const unsigned int fx1 = f[k] & 0xFF00FF00u;
        __half2 s = __hmul2(as_h2(ex0), w00);
        s = __hfma2(as_h2(ex1), w01, s);
        s = __hfma2(as_h2(fx0), w10, s);
        s2[k] = __hfma2(as_h2(fx1), w11, s);
    }
}

__global__ void __launch_bounds__(256, 8) sample_kernel(const float* __restrict__ pts,
                                                        float* __restrict__ out) {
    const int tid = blockIdx.x * blockDim.x + threadIdx.x;
    const int j = tid & 3;             // rank octet 0..3 (8 ranks each)
    const int point = tid >> 2;        // 4 lanes per point

    const float px = __ldg(&pts[point * 3 + 0]);
    const float py = __ldg(&pts[point * 3 + 1]);
    const float pz = __ldg(&pts[point * 3 + 2]);

    const float4 K = g_map[0];
    const float4 O = g_map[1];
    const float gxc = fmaf(px, K.x, O.x);
    const float gyc = fmaf(py, K.y, O.y);
    const float gzc = fmaf(pz, K.z, O.z);

    const Corners cxy = make_corners(gxc, gyc);
    const Corners cxz = make_corners(gxc, gzc);
    const Corners cyz = make_corners(gyc, gzc);

    const char* __restrict__ P0 = reinterpret_cast<const char*>(g_tp[0]);
    const char* __restrict__ P1 = reinterpret_cast<const char*>(g_tp[1]);
    const char* __restrict__ P2 = reinterpret_cast<const char*>(g_tp[2]);
    const unsigned int lo = (unsigned int)j << 4;

    // 6 loads; each covers a full 64 B cell entry across the 4-lane group
    const uint4 E0 = *reinterpret_cast<const uint4*>(P0 + cxy.o0 + lo);
    const uint4 F0 = *reinterpret_cast<const uint4*>(P0 + cxy.o1 + lo);
    const uint4 E1 = *reinterpret_cast<const uint4*>(P1 + cxz.o0 + lo);
    const uint4 F1 = *reinterpret_cast<const uint4*>(P1 + cxz.o1 + lo);
    const uint4 E2 = *reinterpret_cast<const uint4*>(P2 + cyz.o0 + lo);
    const uint4 F2 = *reinterpret_cast<const uint4*>(P2 + cyz.o1 + lo);

    // Weights built in fp16: 2 HSUB2 + 4 HMUL2 per plane
    const __half2 ONE = __float2half2_rn(1.0f);
    const __half2 ox0 = __hsub2(ONE, cxy.wx2), oy0 = __hsub2(ONE, cxy.wy2);
    const __half2 ox1 = __hsub2(ONE, cxz.wx2), oy1 = __hsub2(ONE, cxz.wy2);
    const __half2 ox2 = __hsub2(ONE, cyz.wx2), oy2 = __hsub2(ONE, cyz.wy2);

    __half2 sA[4], sB[4], sC[4];
    plane_sample(E0, F0, __hmul2(ox0, oy0), __hmul2(cxy.wx2, oy0),
                 __hmul2(ox0, cxy.wy2), __hmul2(cxy.wx2, cxy.wy2), sA);
    plane_sample(E1, F1, __hmul2(ox1, oy1), __hmul2(cxz.wx2, oy1),
                 __hmul2(ox1, cxz.wy2), __hmul2(cxz.wx2, cxz.wy2), sB);
    plane_sample(E2, F2, __hmul2(ox2, oy2), __hmul2(cyz.wx2, oy2),
                 __hmul2(ox2, cyz.wy2), __hmul2(cyz.wx2, cyz.wy2), sC);

    // Triple product + accumulate, 2 ranks per op
    __half2 acc = __hmul2(__hmul2(sA[0], sB[0]), sC[0]);
#pragma unroll
    for (int k = 1; k < 4; k++) {
        acc = __hfma2(__hmul2(sA[k], sB[k]), sC[k], acc);
    }
    float sum = __low2float(acc) + __high2float(acc);

    // Reduce across the 4-lane group
    sum += __shfl_xor_sync(0xffffffffu, sum, 1, 4);
    sum += __shfl_xor_sync(0xffffffffu, sum, 2, 4);

    if (j == 0) {
        out[point] = __expf(sum * (1.0f / (float)RANK));
    }
}

extern "C" void kernel_launch(void* const* d_in, const int* in_sizes, int n_in,
                              void* d_out, int out_size) {
    const float* pts  = (const float*)d_in[0];
    const float* gxy  = (const float*)d_in[1];
    const float* gxz  = (const float*)d_in[2];
    const float* gyz  = (const float*)d_in[3];
    const float* aabb = (const float*)d_in[4];
    float* out = (float*)d_out;

    bbox_kernel<<<256, 256>>>((const float4*)pts, aabb);
    transpose_kernel<<<dim3(CELLS / 64, 3), 256>>>(gxy, gxz, gyz, aabb);

    // 4 lanes/point -> 64 points per 256-thread block
    sample_kernel<<<N_POINTS / 64, 256>>>(pts, out);
}

// round 13
// speedup vs baseline: 1.6534x; 1.0042x over previous
#include <cuda_runtime.h>
#include <cuda_fp16.h>

#define RES 512
#define RANK 32
#define CELLS (RES * RES)
#define N_POINTS (8192 * 128)

// e5m2 dup-pair layout: per plane, per cell (y,x): 64 bytes.
// Word k of 16B group j holds bytes [r@x0, r@x1, r+1@x0, r+1@x1], r = 8j+2k.
// e5m2 byte b decodes EXACTLY to the fp16 with bits (b << 8).
__device__ unsigned char g_tp[3][(size_t)CELLS * 2 * RANK];

// Encoded per-dim bbox of raw pts. Static init; graph replays are idempotent
// (atomicMin/Max of the same data over its own result is a fixed point).
__device__ unsigned int g_bbox[6] = {0xFFFFFFFFu, 0xFFFFFFFFu, 0xFFFFFFFFu, 0u, 0u, 0u};

// Affine map: grid = p * g_map[0].{x,y,z} + g_map[1].{x,y,z}
__device__ float4 g_map[2];

__device__ __forceinline__ unsigned int encodeF(float f) {
    unsigned int b = __float_as_uint(f);
    return (b & 0x80000000u) ? ~b : (b | 0x80000000u);
}
__device__ __forceinline__ float decodeF(unsigned int u) {
    return (u & 0x80000000u) ? __uint_as_float(u ^ 0x80000000u)
                             : __uint_as_float(~u);
}

// f32 -> e5m2 byte, round-to-nearest via fp16 + mantissa-rounding add.
__device__ __forceinline__ unsigned int enc_e5m2(float v) {
    const unsigned int u = (unsigned int)__half_as_ushort(__float2half_rn(v));
    return ((u + 0x80u) >> 8) & 0xFFu;
}

// ---------------------------------------------------------------------------
// Kernel 1: per-dimension min/max of raw pts + g_map compute (thread 0).
// ONE group (3 float4 = 4 points) per thread: 262144 threads = 1024 blocks.
// Fixed dim pattern: f4[0]=(x,y,z,x) f4[1]=(y,z,x,y) f4[2]=(z,x,y,z).
// ---------------------------------------------------------------------------
__global__ void __launch_bounds__(256) bbox_kernel(const float4* __restrict__ pts4,
                                                   const float* __restrict__ aabb) {
    const int g = blockIdx.x * 256 + threadIdx.x;        // group id, 0..262143
    if (g == 0) {   // former init_kernel's g_map computation
        float k[3], o[3];
#pragma unroll
        for (int d = 0; d < 3; d++) {
            const float a0 = aabb[d], a1 = aabb[3 + d];
            k[d] = (float)(RES - 1) / (a1 - a0);
            o[d] = -a0 * k[d];
        }
        g_map[0] = make_float4(k[0], k[1], k[2], 0.0f);
        g_map[1] = make_float4(o[0], o[1], o[2], 0.0f);
    }

    const float4 a = __ldg(&pts4[3 * g + 0]);
    const float4 b = __ldg(&pts4[3 * g + 1]);
    const float4 c = __ldg(&pts4[3 * g + 2]);
    const float mnx = fminf(fminf(a.x, a.w), fminf(b.z, c.y));
    const float mxx = fmaxf(fmaxf(a.x, a.w), fmaxf(b.z, c.y));
    const float mny = fminf(fminf(a.y, b.x), fminf(b.w, c.z));
    const float mxy = fmaxf(fmaxf(a.y, b.x), fmaxf(b.w, c.z));
    const float mnz = fminf(fminf(a.z, b.y), fminf(c.x, c.w));
    const float mxz = fmaxf(fmaxf(a.z, b.y), fmaxf(c.x, c.w));

    __shared__ unsigned int smn[3], smx[3];
    if (threadIdx.x < 3) { smn[threadIdx.x] = 0xFFFFFFFFu; smx[threadIdx.x] = 0u; }
    __syncthreads();
    atomicMin(&smn[0], encodeF(mnx));
    atomicMin(&smn[1], encodeF(mny));
    atomicMin(&smn[2], encodeF(mnz));
    atomicMax(&smx[0], encodeF(mxx));
    atomicMax(&smx[1], encodeF(mxy));
    atomicMax(&smx[2], encodeF(mxz));
    __syncthreads();
    if (threadIdx.x < 3) {
        atomicMin(&g_bbox[threadIdx.x], smn[threadIdx.x]);
        atomicMax(&g_bbox[3 + threadIdx.x], smx[threadIdx.x]);
    }
}

// ---------------------------------------------------------------------------
// Kernel 2: [RANK,H,W] f32 -> e5m2 dup-pair layout, bbox-gated.
// ---------------------------------------------------------------------------
__global__ void __launch_bounds__(256) transpose_kernel(const float* __restrict__ gxy,
                                                        const float* __restrict__ gxz,
                                                        const float* __restrict__ gyz,
                                                        const float* __restrict__ aabb) {
    const int plane = blockIdx.y;
    const int c0 = blockIdx.x * 64;
    const int row = c0 >> 9;
    const int col0 = c0 & (RES - 1);

    const int cdim = (plane == 2) ? 1 : 0;
    const int rdim = (plane == 0) ? 1 : 2;

    {   // bbox gate
        const float a0c = aabb[cdim], sc = (float)(RES - 1) / (aabb[3 + cdim] - aabb[cdim]);
        const float a0r = aabb[rdim], sr = (float)(RES - 1) / (aabb[3 + rdim] - aabb[rdim]);
        const float gminc = (decodeF(g_bbox[cdim]) - a0c) * sc;
        const float gmaxc = (decodeF(g_bbox[3 + cdim]) - a0c) * sc;
        const float gminr = (decodeF(g_bbox[rdim]) - a0r) * sr;
        const float gmaxr = (decodeF(g_bbox[3 + rdim]) - a0r) * sr;
        const int cmin = min(max(__float2int_rd(gminc), 0), RES - 1);
        const int cmax = min(min(max(__float2int_rd(gmaxc), 0), RES - 1) + 1, RES - 1);
        const int rmin = min(max(__float2int_rd(gminr), 0), RES - 1);
        const int rmax = min(min(max(__float2int_rd(gmaxr), 0), RES - 1) + 1, RES - 1);
        if (row < rmin || row > rmax || col0 > cmax || col0 + 63 < cmin) return;
    }

    __shared__ float tile[RANK][67];
    const float* __restrict__ src = (plane == 0) ? gxy : (plane == 1) ? gxz : gyz;

    const int t = threadIdx.x;

    // Load 32 ranks x 64 cols via float4
#pragma unroll
    for (int i = 0; i < 2; i++) {
        const int q = t + i * 256;
        const int r = q >> 4;
        const int c4 = (q & 15) << 2;
        const float4 v = *reinterpret_cast<const float4*>(&src[(size_t)r * CELLS + c0 + c4]);
        tile[r][c4 + 0] = v.x;
        tile[r][c4 + 1] = v.y;
        tile[r][c4 + 2] = v.z;
        tile[r][c4 + 3] = v.w;
    }
    if (t < RANK) {
        const int srccol = (col0 + 64 <= RES - 1) ? (c0 + 64) : (c0 + 63);
        tile[t][64] = src[(size_t)t * CELLS + srccol];
    }
    __syncthreads();

    {
        const int cell = t >> 2;
        const int j = t & 3;
        const int xg = col0 + cell;
        const int nb = (xg < RES - 1) ? cell + 1 : cell;
        uint4 w;
        unsigned int* wp = &w.x;
#pragma unroll
        for (int k = 0; k < 4; k++) {
            const int r0 = 8 * j + 2 * k;
            const unsigned int b0 = enc_e5m2(tile[r0][cell]);
            const unsigned int b1 = enc_e5m2(tile[r0][nb]);
            const unsigned int b2 = enc_e5m2(tile[r0 + 1][cell]);
            const unsigned int b3 = enc_e5m2(tile[r0 + 1][nb]);
            wp[k] = b0 | (b1 << 8) | (b2 << 16) | (b3 << 24);
        }
        *reinterpret_cast<uint4*>(&g_tp[plane][((size_t)(c0 + cell) << 6) + (j << 4)]) = w;
    }
}

// ---------------------------------------------------------------------------
// Kernel 3: triplane sample. 4 lanes/point; lane j = ranks 8j..8j+7.
// __launch_bounds__(256, 8): cap at 32 regs so 8 blocks (64 warps) fit per SM.
// ---------------------------------------------------------------------------
struct Corners {
    unsigned int o0, o1;   // byte offsets of (y0,x0) and (y1,x0) entries
    __half2 wx2, wy2;      // duplicated fractional weights
};

// gx/gy are final grid coords (already affinely mapped).
__device__ __forceinline__ Corners make_corners(float gx, float gy) {
    Corners c;
    c.wx2 = __float2half2_rn(gx - floorf(gx));
    c.wy2 = __float2half2_rn(gy - floorf(gy));
    const int x0 = min(max(__float2int_rd(gx), 0), RES - 1);
    const int y0 = min(max(__float2int_rd(gy), 0), RES - 1);
    const unsigned int dy = (y0 < RES - 1) ? 32768u : 0u;   // 512*64 B row stride
    c.o0 = (unsigned int)(((y0 << 9) + x0) << 6);
    c.o1 = c.o0 + dy;
    return c;
}

__device__ __forceinline__ __half2 as_h2(unsigned int u) {
    return *reinterpret_cast<__half2*>(&u);
}

// s2[k] = bilinear samples of ranks (8j+2k, 8j+2k+1), fully interpolated.
__device__ __forceinline__ void plane_sample(const uint4& E, const uint4& F,
                                             __half2 w00, __half2 w01,
                                             __half2 w10, __half2 w11,
                                             __half2 s2[4]) {
    const unsigned int* e = &E.x;
    const unsigned int* f = &F.x;
#pragma unroll
    for (int k = 0; k < 4; k++) {
        const unsigned int ex0 = __byte_perm(e[k], 0, 0x2404);  // (r@x0, r+1@x0)
        const unsigned int ex1 = e[k] & 0xFF00FF00u;            // (r@x1, r+1@x1)
        const unsigned int fx0 = __byte_perm(f[k], 0, 0x2404);
        const unsigned int fx1 = f[k] & 0xFF00FF00u;
        __half2 s = __hmul2(as_h2(ex0), w00);
        s = __hfma2(as_h2(ex1), w01, s);
        s = __hfma2(as_h2(fx0), w10, s);
        s2[k] = __hfma2(as_h2(fx1), w11, s);
    }
}

__global__ void __launch_bounds__(256, 8) sample_kernel(const float* __restrict__ pts,
                                                        float* __restrict__ out) {
    const int tid = blockIdx.x * blockDim.x + threadIdx.x;
    const int j = tid & 3;             // rank octet 0..3 (8 ranks each)
    const int point = tid >> 2;        // 4 lanes per point

    const float px = __ldg(&pts[point * 3 + 0]);
    const float py = __ldg(&pts[point * 3 + 1]);
    const float pz = __ldg(&pts[point * 3 + 2]);

    const float4 K = g_map[0];
    const float4 O = g_map[1];
    const float gxc = fmaf(px, K.x, O.x);
    const float gyc = fmaf(py, K.y, O.y);
    const float gzc = fmaf(pz, K.z, O.z);

    const Corners cxy = make_corners(gxc, gyc);
    const Corners cxz = make_corners(gxc, gzc);
    const Corners cyz = make_corners(gyc, gzc);

    const char* __restrict__ P0 = reinterpret_cast<const char*>(g_tp[0]);
    const char* __restrict__ P1 = reinterpret_cast<const char*>(g_tp[1]);
    const char* __restrict__ P2 = reinterpret_cast<const char*>(g_tp[2]);
    const unsigned int lo = (unsigned int)j << 4;

    // 6 loads; each covers a full 64 B cell entry across the 4-lane group
    const uint4 E0 = *reinterpret_cast<const uint4*>(P0 + cxy.o0 + lo);
    const uint4 F0 = *reinterpret_cast<const uint4*>(P0 + cxy.o1 + lo);
    const uint4 E1 = *reinterpret_cast<const uint4*>(P1 + cxz.o0 + lo);
    const uint4 F1 = *reinterpret_cast<const uint4*>(P1 + cxz.o1 + lo);
    const uint4 E2 = *reinterpret_cast<const uint4*>(P2 + cyz.o0 + lo);
    const uint4 F2 = *reinterpret_cast<const uint4*>(P2 + cyz.o1 + lo);

    // Weights built in fp16: 2 HSUB2 + 4 HMUL2 per plane
    const __half2 ONE = __float2half2_rn(1.0f);
    const __half2 ox0 = __hsub2(ONE, cxy.wx2), oy0 = __hsub2(ONE, cxy.wy2);
    const __half2 ox1 = __hsub2(ONE, cxz.wx2), oy1 = __hsub2(ONE, cxz.wy2);
    const __half2 ox2 = __hsub2(ONE, cyz.wx2), oy2 = __hsub2(ONE, cyz.wy2);

    __half2 sA[4], sB[4], sC[4];
    plane_sample(E0, F0, __hmul2(ox0, oy0), __hmul2(cxy.wx2, oy0),
                 __hmul2(ox0, cxy.wy2), __hmul2(cxy.wx2, cxy.wy2), sA);
    plane_sample(E1, F1, __hmul2(ox1, oy1), __hmul2(cxz.wx2, oy1),
                 __hmul2(ox1, cxz.wy2), __hmul2(cxz.wx2, cxz.wy2), sB);
    plane_sample(E2, F2, __hmul2(ox2, oy2), __hmul2(cyz.wx2, oy2),
                 __hmul2(ox2, cyz.wy2), __hmul2(cyz.wx2, cyz.wy2), sC);

    // Triple product + accumulate, 2 ranks per op
    __half2 acc = __hmul2(__hmul2(sA[0], sB[0]), sC[0]);
#pragma unroll
    for (int k = 1; k < 4; k++) {
        acc = __hfma2(__hmul2(sA[k], sB[k]), sC[k], acc);
    }
    float sum = __low2float(acc) + __high2float(acc);

    // Reduce across the 4-lane group
    sum += __shfl_xor_sync(0xffffffffu, sum, 1, 4);
    sum += __shfl_xor_sync(0xffffffffu, sum, 2, 4);

    if (j == 0) {
        out[point] = __expf(sum * (1.0f / (float)RANK));
    }
}

extern "C" void kernel_launch(void* const* d_in, const int* in_sizes, int n_in,
                              void* d_out, int out_size) {
    const float* pts  = (const float*)d_in[0];
    const float* gxy  = (const float*)d_in[1];
    const float* gxz  = (const float*)d_in[2];
    const float* gyz  = (const float*)d_in[3];
    const float* aabb = (const float*)d_in[4];
    float* out = (float*)d_out;

    // 262144 groups, 1 per thread
    bbox_kernel<<<1024, 256>>>((const float4*)pts, aabb);
    transpose_kernel<<<dim3(CELLS / 64, 3), 256>>>(gxy, gxz, gyz, aabb);

    // 4 lanes/point -> 64 points per 256-thread block
    sample_kernel<<<N_POINTS / 64, 256>>>(pts, out);
}